// round 1
// baseline (speedup 1.0000x reference)
#include <cuda_runtime.h>
#include <math.h>

// Problem constants (fixed by the reference)
#define BB    2
#define LL    1024
#define DM    1024
#define ED    2048
#define NS    16
#define DTR   64
#define TOK   (BB*LL)          // 2048 tokens
#define XPW   (DTR + 2*NS)     // 96

// -------- scratch (no allocation allowed; device globals) --------
__device__ float g_xz[(size_t)TOK * 2 * ED];   // 32 MB : in_proj output [tok][4096]
__device__ float g_xc[(size_t)TOK * ED];       // 16 MB : conv+silu output
__device__ float g_dbc[(size_t)TOK * XPW];     //        : x_proj output [tok][96]
__device__ float g_delta[(size_t)TOK * ED];    // 16 MB : softplus(dt_proj)
__device__ float g_y[(size_t)TOK * ED];        // 16 MB : scan output (pre out_proj)

// ============================================================================
// Classic 128x128x8 SGEMM, 256 threads, 8x8 microtile.
// A: MxK row-major (lda), B: KxN row-major (ldb), C: MxN row-major (ldc).
// All of M,N multiples of 128 and K multiple of 8 (true for every call here).
// EPI: 0 = plain store, 1 = +bias[col] then softplus.
// ============================================================================
template<int EPI>
__global__ void __launch_bounds__(256, 2)
sgemm128(const float* __restrict__ A, const float* __restrict__ B,
         float* __restrict__ C, int M, int N, int K,
         int lda, int ldb, int ldc, const float* __restrict__ bias)
{
    __shared__ __align__(16) float As[8][128];
    __shared__ __align__(16) float Bs[8][128];

    const int tid = threadIdx.x;
    const int bm = blockIdx.y * 128;
    const int bn = blockIdx.x * 128;

    // A tile load: 128 rows x 8 k -> 1 float4/thread
    const int arow = tid >> 1;
    const int acol = (tid & 1) << 2;
    // B tile load: 8 k x 128 cols -> 1 float4/thread
    const int brow = tid >> 5;
    const int bcol = (tid & 31) << 2;

    const float* Ap = A + (size_t)(bm + arow) * lda + acol;
    const float* Bp = B + (size_t)brow * ldb + bn + bcol;

    const int trow = (tid >> 4) << 3;   // 0..120
    const int tcol = (tid & 15) << 3;   // 0..120

    float acc[8][8];
#pragma unroll
    for (int i = 0; i < 8; ++i)
#pragma unroll
        for (int j = 0; j < 8; ++j) acc[i][j] = 0.f;

    for (int k0 = 0; k0 < K; k0 += 8) {
        float4 av = *(const float4*)Ap;
        float4 bv = *(const float4*)Bp;
        As[acol + 0][arow] = av.x;
        As[acol + 1][arow] = av.y;
        As[acol + 2][arow] = av.z;
        As[acol + 3][arow] = av.w;
        *(float4*)&Bs[brow][bcol] = bv;
        __syncthreads();

#pragma unroll
        for (int k = 0; k < 8; ++k) {
            float4 a0 = *(const float4*)&As[k][trow];
            float4 a1 = *(const float4*)&As[k][trow + 4];
            float4 b0 = *(const float4*)&Bs[k][tcol];
            float4 b1 = *(const float4*)&Bs[k][tcol + 4];
            float a[8] = {a0.x, a0.y, a0.z, a0.w, a1.x, a1.y, a1.z, a1.w};
            float b[8] = {b0.x, b0.y, b0.z, b0.w, b1.x, b1.y, b1.z, b1.w};
#pragma unroll
            for (int i = 0; i < 8; ++i)
#pragma unroll
                for (int j = 0; j < 8; ++j)
                    acc[i][j] = fmaf(a[i], b[j], acc[i][j]);
        }
        __syncthreads();
        Ap += 8;
        Bp += (size_t)8 * ldb;
    }

#pragma unroll
    for (int i = 0; i < 8; ++i) {
        float out[8];
#pragma unroll
        for (int j = 0; j < 8; ++j) {
            float v = acc[i][j];
            if (EPI == 1) {
                v += bias[bn + tcol + j];
                v = (v > 20.f) ? v : log1pf(expf(v));  // softplus
            }
            out[j] = v;
        }
        float* cp = C + (size_t)(bm + trow + i) * ldc + bn + tcol;
        *(float4*)(cp)     = make_float4(out[0], out[1], out[2], out[3]);
        *(float4*)(cp + 4) = make_float4(out[4], out[5], out[6], out[7]);
    }
}

// ============================================================================
// Depthwise causal conv1d (k=4, left pad 3) + bias + SiLU.
// Reads first half of g_xz (columns [0, ED)), writes g_xc.
// ============================================================================
__global__ void conv_silu_kernel(const float* __restrict__ cw,
                                 const float* __restrict__ cb)
{
    int idx = blockIdx.x * blockDim.x + threadIdx.x;
    if (idx >= TOK * ED) return;
    int e = idx & (ED - 1);
    int t = idx >> 11;          // token index 0..2047
    int l = t & (LL - 1);       // position within batch

    float w0 = cw[e * 4 + 0], w1 = cw[e * 4 + 1];
    float w2 = cw[e * 4 + 2], w3 = cw[e * 4 + 3];

    const float* col = g_xz + (size_t)t * (2 * ED) + e;
    float acc = cb[e] + w3 * col[0];                      // x[l]   * w[3]
    if (l >= 1) acc = fmaf(w2, col[-(2 * ED)],     acc);  // x[l-1] * w[2]
    if (l >= 2) acc = fmaf(w1, col[-2 * (2 * ED)], acc);  // x[l-2] * w[1]
    if (l >= 3) acc = fmaf(w0, col[-3 * (2 * ED)], acc);  // x[l-3] * w[0]

    g_xc[(size_t)t * ED + e] = acc / (1.f + __expf(-acc));  // silu
}

// ============================================================================
// x_proj: dbc[tok][96] = xc[tok][2048] @ W[2048][96]
// Grid: 128 blocks (M tile = 16), 256 threads, K staged in chunks of 32.
// ============================================================================
__global__ void __launch_bounds__(256)
xproj_kernel(const float* __restrict__ W)
{
    __shared__ __align__(16) float Xs[16][32];
    __shared__ __align__(16) float Ws[32][XPW];

    const int tid = threadIdx.x;
    const int bm = blockIdx.x * 16;
    const int row = tid >> 4;          // 0..15
    const int cb  = (tid & 15) * 6;    // 0..90

    float acc[6] = {0, 0, 0, 0, 0, 0};

    for (int k0 = 0; k0 < ED; k0 += 32) {
        if (tid < 128) {
            int r = tid >> 3, c = (tid & 7) << 2;
            *(float4*)&Xs[r][c] =
                *(const float4*)(g_xc + (size_t)(bm + r) * ED + k0 + c);
        }
        for (int i = tid; i < 32 * (XPW / 4); i += 256) {  // 768 float4s
            int r = i / 24, c = (i % 24) << 2;
            *(float4*)&Ws[r][c] = *(const float4*)(W + (size_t)(k0 + r) * XPW + c);
        }
        __syncthreads();
#pragma unroll 8
        for (int kk = 0; kk < 32; ++kk) {
            float a = Xs[row][kk];
#pragma unroll
            for (int j = 0; j < 6; ++j)
                acc[j] = fmaf(a, Ws[kk][cb + j], acc[j]);
        }
        __syncthreads();
    }
#pragma unroll
    for (int j = 0; j < 6; ++j)
        g_dbc[(size_t)(bm + row) * XPW + cb + j] = acc[j];
}

// ============================================================================
// Selective scan. One 16-lane group per (b, ed) chain; lane = state index n.
// h_n(t) = exp(delta*A_n)*h_n(t-1) + delta*B_n(t)*xc(t)
// y = (sum_n h_n*C_n + D*xc) * silu(z)
// ============================================================================
__global__ void __launch_bounds__(256)
scan_kernel(const float* __restrict__ A_log, const float* __restrict__ Dvec)
{
    const int tid  = threadIdx.x;
    const int g    = blockIdx.x * 16 + (tid >> 4);  // group id, 0..4095
    const int lane = tid & 15;
    const int b    = g >> 11;         // / ED
    const int ed   = g & (ED - 1);

    const float An = -__expf(A_log[ed * NS + lane]);
    const float Dv = Dvec[ed];

    const float* dptr  = g_delta + (size_t)(b * LL) * ED + ed;
    const float* xptr  = g_xc    + (size_t)(b * LL) * ED + ed;
    const float* zptr  = g_xz    + (size_t)(b * LL) * (2 * ED) + ED + ed;
    const float* bcptr = g_dbc   + (size_t)(b * LL) * XPW + DTR + lane;
    float*       yptr  = g_y     + (size_t)(b * LL) * ED + ed;

    float h = 0.f;
#pragma unroll 4
    for (int l = 0; l < LL; ++l) {
        float dv = __ldg(dptr);
        float xv = __ldg(xptr);
        float Bv = __ldg(bcptr);
        float Cv = __ldg(bcptr + NS);

        float da = __expf(dv * An);
        h = fmaf(da, h, dv * Bv * xv);

        float p = h * Cv;
        p += __shfl_xor_sync(0xffffffffu, p, 1);
        p += __shfl_xor_sync(0xffffffffu, p, 2);
        p += __shfl_xor_sync(0xffffffffu, p, 4);
        p += __shfl_xor_sync(0xffffffffu, p, 8);

        if (lane == 0) {
            float zv = __ldg(zptr);
            float s  = zv / (1.f + __expf(-zv));     // silu(z)
            *yptr = (p + Dv * xv) * s;
        }
        dptr  += ED;
        xptr  += ED;
        zptr  += 2 * ED;
        bcptr += XPW;
        yptr  += ED;
    }
}

// ============================================================================
extern "C" void kernel_launch(void* const* d_in, const int* in_sizes, int n_in,
                              void* d_out, int out_size)
{
    const float* x         = (const float*)d_in[0];
    const float* in_proj_w = (const float*)d_in[1];
    const float* conv_w    = (const float*)d_in[2];
    const float* conv_b    = (const float*)d_in[3];
    const float* x_proj_w  = (const float*)d_in[4];
    const float* dt_proj_w = (const float*)d_in[5];
    const float* dt_proj_b = (const float*)d_in[6];
    const float* A_log     = (const float*)d_in[7];
    const float* Dvec      = (const float*)d_in[8];
    const float* out_proj_w= (const float*)d_in[9];
    float* out = (float*)d_out;

    static float *p_xz = nullptr, *p_dbc = nullptr, *p_delta = nullptr, *p_y = nullptr;
    if (!p_xz) {
        cudaGetSymbolAddress((void**)&p_xz,    g_xz);
        cudaGetSymbolAddress((void**)&p_dbc,   g_dbc);
        cudaGetSymbolAddress((void**)&p_delta, g_delta);
        cudaGetSymbolAddress((void**)&p_y,     g_y);
    }

    // 1) xz = x @ in_proj_w : (2048x1024)@(1024x4096)
    sgemm128<0><<<dim3(2 * ED / 128, TOK / 128), 256>>>(
        x, in_proj_w, p_xz, TOK, 2 * ED, DM, DM, 2 * ED, 2 * ED, nullptr);

    // 2) depthwise causal conv + silu -> g_xc
    conv_silu_kernel<<<(TOK * ED + 255) / 256, 256>>>(conv_w, conv_b);

    // 3) dbc = xc @ x_proj_w : (2048x2048)@(2048x96)
    xproj_kernel<<<TOK / 16, 256>>>(x_proj_w);

    // 4) delta = softplus(dbc[:, :64] @ dt_proj_w + dt_proj_b)
    sgemm128<1><<<dim3(ED / 128, TOK / 128), 256>>>(
        p_dbc, dt_proj_w, p_delta, TOK, ED, DTR, XPW, ED, ED, dt_proj_b);

    // 5) selective scan -> g_y
    scan_kernel<<<(BB * ED) / 16, 256>>>(A_log, Dvec);

    // 6) out = y @ out_proj_w : (2048x2048)@(2048x1024)
    sgemm128<0><<<dim3(DM / 128, TOK / 128), 256>>>(
        p_y, out_proj_w, out, TOK, DM, ED, ED, DM, DM, nullptr);
}

// round 2
// speedup vs baseline: 1.3694x; 1.3694x over previous
#include <cuda_runtime.h>
#include <math.h>
#include <stdint.h>

// Problem constants (fixed by the reference)
#define BB    2
#define LL    1024
#define DM    1024
#define ED    2048
#define NS    16
#define DTR   64
#define TOK   (BB*LL)          // 2048 tokens
#define XPW   (DTR + 2*NS)     // 96

// -------- scratch (no allocation allowed; device globals) --------
__device__ float g_xz[(size_t)TOK * 2 * ED];   // 32 MB : in_proj output [tok][4096]
__device__ float g_xc[(size_t)TOK * ED];       // 16 MB : conv+silu output
__device__ float g_dbc[(size_t)TOK * XPW];     //        : x_proj output [tok][96]
__device__ float g_delta[(size_t)TOK * ED];    // 16 MB : softplus(dt_proj)
__device__ float g_y[(size_t)TOK * ED];        // 16 MB : scan output (pre out_proj)

// ============================================================================
// TF32 tensor-core GEMM: 128x128 tile, BK=16, 256 threads (8 warps),
// warp tile 64x32 via mma.sync.aligned.m16n8k8 tf32.
// A: MxK row-major (lda), B: KxN row-major (ldb), C: MxN row-major (ldc).
// M,N multiples of 128; K multiple of 16. Inputs converted fp32->tf32 (RNA)
// on the gmem->smem path. EPI: 0 = plain store, 1 = +bias[col] + softplus.
// ============================================================================
__device__ __forceinline__ uint32_t f2tf32(float f) {
    uint32_t u;
    asm("cvt.rna.tf32.f32 %0, %1;" : "=r"(u) : "f"(f));
    return u;
}

#define SMP 132   // padded smem row stride (floats)

template<int EPI>
__global__ void __launch_bounds__(256)
gemm_tf32(const float* __restrict__ A, const float* __restrict__ B,
          float* __restrict__ C, int M, int N, int K,
          int lda, int ldb, int ldc, const float* __restrict__ bias)
{
    // As[buf][k][m], Bs[buf][k][n] — k-major, padded to 132 to break conflicts
    __shared__ __align__(16) uint32_t As[2][16 * SMP];
    __shared__ __align__(16) uint32_t Bs[2][16 * SMP];

    const int tid  = threadIdx.x;
    const int lane = tid & 31;
    const int wid  = tid >> 5;
    const int lm   = lane >> 2;   // 0..7
    const int lk   = lane & 3;    // 0..3

    const int bm = blockIdx.y * 128;
    const int bn = blockIdx.x * 128;
    const int wm = (wid >> 2) * 64;   // warp row offset (0 or 64)
    const int wn = (wid & 3) * 32;    // warp col offset (0,32,64,96)

    // gmem load geometry
    const int ar = tid >> 2;          // A rows: ar, ar+64
    const int ac = (tid & 3) << 2;    // A col within BK tile
    const int br = tid >> 5;          // B rows: br, br+8
    const int bc = (tid & 31) << 2;   // B col within BN tile

    const float* Ap = A + (size_t)(bm + ar) * lda + ac;
    const float* Bp = B + (size_t)br * ldb + bn + bc;

    float acc[4][4][4];
#pragma unroll
    for (int i = 0; i < 4; ++i)
#pragma unroll
        for (int j = 0; j < 4; ++j)
#pragma unroll
            for (int r = 0; r < 4; ++r) acc[i][j][r] = 0.f;

    const int KT = K / 16;

    // ---- prologue: load tile 0 ----
    float4 a0 = *(const float4*)Ap;
    float4 a1 = *(const float4*)(Ap + (size_t)64 * lda);
    float4 b0 = *(const float4*)Bp;
    float4 b1 = *(const float4*)(Bp + (size_t)8 * ldb);

    int buf = 0;
    {
#pragma unroll
        for (int i = 0; i < 4; ++i) {
            float va = (i == 0) ? a0.x : (i == 1) ? a0.y : (i == 2) ? a0.z : a0.w;
            float vb = (i == 0) ? a1.x : (i == 1) ? a1.y : (i == 2) ? a1.z : a1.w;
            As[0][(ac + i) * SMP + ar]      = f2tf32(va);
            As[0][(ac + i) * SMP + ar + 64] = f2tf32(vb);
        }
        uint4 ub0 = make_uint4(f2tf32(b0.x), f2tf32(b0.y), f2tf32(b0.z), f2tf32(b0.w));
        uint4 ub1 = make_uint4(f2tf32(b1.x), f2tf32(b1.y), f2tf32(b1.z), f2tf32(b1.w));
        *(uint4*)&Bs[0][br * SMP + bc]       = ub0;
        *(uint4*)&Bs[0][(br + 8) * SMP + bc] = ub1;
    }
    __syncthreads();

    for (int kt = 0; kt < KT; ++kt) {
        // prefetch next tile into registers
        if (kt + 1 < KT) {
            const float* Apn = Ap + (kt + 1) * 16;
            const float* Bpn = Bp + (size_t)(kt + 1) * 16 * ldb;
            a0 = *(const float4*)Apn;
            a1 = *(const float4*)(Apn + (size_t)64 * lda);
            b0 = *(const float4*)Bpn;
            b1 = *(const float4*)(Bpn + (size_t)8 * ldb);
        }

        // compute on current buffer
        const uint32_t* Asb = As[buf];
        const uint32_t* Bsb = Bs[buf];
#pragma unroll
        for (int kb = 0; kb < 16; kb += 8) {
            uint32_t af[4][4], bf[4][2];
#pragma unroll
            for (int mt = 0; mt < 4; ++mt) {
                int m = wm + mt * 16 + lm;
                af[mt][0] = Asb[(kb + lk) * SMP + m];
                af[mt][1] = Asb[(kb + lk) * SMP + m + 8];
                af[mt][2] = Asb[(kb + 4 + lk) * SMP + m];
                af[mt][3] = Asb[(kb + 4 + lk) * SMP + m + 8];
            }
#pragma unroll
            for (int nt = 0; nt < 4; ++nt) {
                int n = wn + nt * 8 + lm;
                bf[nt][0] = Bsb[(kb + lk) * SMP + n];
                bf[nt][1] = Bsb[(kb + 4 + lk) * SMP + n];
            }
#pragma unroll
            for (int mt = 0; mt < 4; ++mt)
#pragma unroll
                for (int nt = 0; nt < 4; ++nt) {
                    asm volatile(
                        "mma.sync.aligned.m16n8k8.row.col.f32.tf32.tf32.f32 "
                        "{%0,%1,%2,%3}, {%4,%5,%6,%7}, {%8,%9}, {%0,%1,%2,%3};\n"
                        : "+f"(acc[mt][nt][0]), "+f"(acc[mt][nt][1]),
                          "+f"(acc[mt][nt][2]), "+f"(acc[mt][nt][3])
                        : "r"(af[mt][0]), "r"(af[mt][1]), "r"(af[mt][2]), "r"(af[mt][3]),
                          "r"(bf[nt][0]), "r"(bf[nt][1]));
                }
        }

        // stage next tile into the other buffer
        if (kt + 1 < KT) {
            int nb = buf ^ 1;
#pragma unroll
            for (int i = 0; i < 4; ++i) {
                float va = (i == 0) ? a0.x : (i == 1) ? a0.y : (i == 2) ? a0.z : a0.w;
                float vb = (i == 0) ? a1.x : (i == 1) ? a1.y : (i == 2) ? a1.z : a1.w;
                As[nb][(ac + i) * SMP + ar]      = f2tf32(va);
                As[nb][(ac + i) * SMP + ar + 64] = f2tf32(vb);
            }
            uint4 ub0 = make_uint4(f2tf32(b0.x), f2tf32(b0.y), f2tf32(b0.z), f2tf32(b0.w));
            uint4 ub1 = make_uint4(f2tf32(b1.x), f2tf32(b1.y), f2tf32(b1.z), f2tf32(b1.w));
            *(uint4*)&Bs[nb][br * SMP + bc]       = ub0;
            *(uint4*)&Bs[nb][(br + 8) * SMP + bc] = ub1;
        }
        __syncthreads();
        buf ^= 1;
    }

    // ---- epilogue ----
#pragma unroll
    for (int mt = 0; mt < 4; ++mt) {
#pragma unroll
        for (int nt = 0; nt < 4; ++nt) {
            int row = bm + wm + mt * 16 + lm;
            int col = bn + wn + nt * 8 + lk * 2;
            float v0 = acc[mt][nt][0], v1 = acc[mt][nt][1];
            float v2 = acc[mt][nt][2], v3 = acc[mt][nt][3];
            if (EPI == 1) {
                float bb0 = bias[col], bb1 = bias[col + 1];
                v0 += bb0; v1 += bb1; v2 += bb0; v3 += bb1;
                v0 = (v0 > 20.f) ? v0 : log1pf(expf(v0));
                v1 = (v1 > 20.f) ? v1 : log1pf(expf(v1));
                v2 = (v2 > 20.f) ? v2 : log1pf(expf(v2));
                v3 = (v3 > 20.f) ? v3 : log1pf(expf(v3));
            }
            *(float2*)(C + (size_t)row * ldc + col)       = make_float2(v0, v1);
            *(float2*)(C + (size_t)(row + 8) * ldc + col) = make_float2(v2, v3);
        }
    }
}

// ============================================================================
// Depthwise causal conv1d (k=4, left pad 3) + bias + SiLU.
// ============================================================================
__global__ void conv_silu_kernel(const float* __restrict__ cw,
                                 const float* __restrict__ cb)
{
    int idx = blockIdx.x * blockDim.x + threadIdx.x;
    if (idx >= TOK * ED) return;
    int e = idx & (ED - 1);
    int t = idx >> 11;          // token index 0..2047
    int l = t & (LL - 1);       // position within batch

    float w0 = cw[e * 4 + 0], w1 = cw[e * 4 + 1];
    float w2 = cw[e * 4 + 2], w3 = cw[e * 4 + 3];

    const float* col = g_xz + (size_t)t * (2 * ED) + e;
    float acc = cb[e] + w3 * col[0];
    if (l >= 1) acc = fmaf(w2, col[-(2 * ED)],     acc);
    if (l >= 2) acc = fmaf(w1, col[-2 * (2 * ED)], acc);
    if (l >= 3) acc = fmaf(w0, col[-3 * (2 * ED)], acc);

    g_xc[(size_t)t * ED + e] = acc / (1.f + __expf(-acc));  // silu
}

// ============================================================================
// x_proj: dbc[tok][96] = xc[tok][2048] @ W[2048][96]
// ============================================================================
__global__ void __launch_bounds__(256)
xproj_kernel(const float* __restrict__ W)
{
    __shared__ __align__(16) float Xs[16][32];
    __shared__ __align__(16) float Ws[32][XPW];

    const int tid = threadIdx.x;
    const int bm = blockIdx.x * 16;
    const int row = tid >> 4;          // 0..15
    const int cb  = (tid & 15) * 6;    // 0..90

    float acc[6] = {0, 0, 0, 0, 0, 0};

    for (int k0 = 0; k0 < ED; k0 += 32) {
        if (tid < 128) {
            int r = tid >> 3, c = (tid & 7) << 2;
            *(float4*)&Xs[r][c] =
                *(const float4*)(g_xc + (size_t)(bm + r) * ED + k0 + c);
        }
        for (int i = tid; i < 32 * (XPW / 4); i += 256) {
            int r = i / 24, c = (i % 24) << 2;
            *(float4*)&Ws[r][c] = *(const float4*)(W + (size_t)(k0 + r) * XPW + c);
        }
        __syncthreads();
#pragma unroll 8
        for (int kk = 0; kk < 32; ++kk) {
            float a = Xs[row][kk];
#pragma unroll
            for (int j = 0; j < 6; ++j)
                acc[j] = fmaf(a, Ws[kk][cb + j], acc[j]);
        }
        __syncthreads();
    }
#pragma unroll
    for (int j = 0; j < 6; ++j)
        g_dbc[(size_t)(bm + row) * XPW + cb + j] = acc[j];
}

// ============================================================================
// Selective scan. One 16-lane group per (b, ed) chain; lane = state index n.
// ============================================================================
__global__ void __launch_bounds__(256)
scan_kernel(const float* __restrict__ A_log, const float* __restrict__ Dvec)
{
    const int tid  = threadIdx.x;
    const int g    = blockIdx.x * 16 + (tid >> 4);
    const int lane = tid & 15;
    const int b    = g >> 11;
    const int ed   = g & (ED - 1);

    const float An = -__expf(A_log[ed * NS + lane]);
    const float Dv = Dvec[ed];

    const float* dptr  = g_delta + (size_t)(b * LL) * ED + ed;
    const float* xptr  = g_xc    + (size_t)(b * LL) * ED + ed;
    const float* zptr  = g_xz    + (size_t)(b * LL) * (2 * ED) + ED + ed;
    const float* bcptr = g_dbc   + (size_t)(b * LL) * XPW + DTR + lane;
    float*       yptr  = g_y     + (size_t)(b * LL) * ED + ed;

    float h = 0.f;
#pragma unroll 4
    for (int l = 0; l < LL; ++l) {
        float dv = __ldg(dptr);
        float xv = __ldg(xptr);
        float Bv = __ldg(bcptr);
        float Cv = __ldg(bcptr + NS);

        float da = __expf(dv * An);
        h = fmaf(da, h, dv * Bv * xv);

        float p = h * Cv;
        p += __shfl_xor_sync(0xffffffffu, p, 1);
        p += __shfl_xor_sync(0xffffffffu, p, 2);
        p += __shfl_xor_sync(0xffffffffu, p, 4);
        p += __shfl_xor_sync(0xffffffffu, p, 8);

        if (lane == 0) {
            float zv = __ldg(zptr);
            float s  = zv / (1.f + __expf(-zv));
            *yptr = (p + Dv * xv) * s;
        }
        dptr  += ED;
        xptr  += ED;
        zptr  += 2 * ED;
        bcptr += XPW;
        yptr  += ED;
    }
}

// ============================================================================
extern "C" void kernel_launch(void* const* d_in, const int* in_sizes, int n_in,
                              void* d_out, int out_size)
{
    const float* x         = (const float*)d_in[0];
    const float* in_proj_w = (const float*)d_in[1];
    const float* conv_w    = (const float*)d_in[2];
    const float* conv_b    = (const float*)d_in[3];
    const float* x_proj_w  = (const float*)d_in[4];
    const float* dt_proj_w = (const float*)d_in[5];
    const float* dt_proj_b = (const float*)d_in[6];
    const float* A_log     = (const float*)d_in[7];
    const float* Dvec      = (const float*)d_in[8];
    const float* out_proj_w= (const float*)d_in[9];
    float* out = (float*)d_out;

    static float *p_xz = nullptr, *p_dbc = nullptr, *p_delta = nullptr, *p_y = nullptr;
    if (!p_xz) {
        cudaGetSymbolAddress((void**)&p_xz,    g_xz);
        cudaGetSymbolAddress((void**)&p_dbc,   g_dbc);
        cudaGetSymbolAddress((void**)&p_delta, g_delta);
        cudaGetSymbolAddress((void**)&p_y,     g_y);
    }

    // 1) xz = x @ in_proj_w : (2048x1024)@(1024x4096)
    gemm_tf32<0><<<dim3(2 * ED / 128, TOK / 128), 256>>>(
        x, in_proj_w, p_xz, TOK, 2 * ED, DM, DM, 2 * ED, 2 * ED, nullptr);

    // 2) depthwise causal conv + silu -> g_xc
    conv_silu_kernel<<<(TOK * ED + 255) / 256, 256>>>(conv_w, conv_b);

    // 3) dbc = xc @ x_proj_w : (2048x2048)@(2048x96)
    xproj_kernel<<<TOK / 16, 256>>>(x_proj_w);

    // 4) delta = softplus(dbc[:, :64] @ dt_proj_w + dt_proj_b)
    gemm_tf32<1><<<dim3(ED / 128, TOK / 128), 256>>>(
        p_dbc, dt_proj_w, p_delta, TOK, ED, DTR, XPW, ED, ED, dt_proj_b);

    // 5) selective scan -> g_y
    scan_kernel<<<(BB * ED) / 16, 256>>>(A_log, Dvec);

    // 6) out = y @ out_proj_w : (2048x2048)@(2048x1024)
    gemm_tf32<0><<<dim3(DM / 128, TOK / 128), 256>>>(
        p_y, out_proj_w, out, TOK, DM, ED, ED, DM, DM, nullptr);
}

// round 3
// speedup vs baseline: 1.4044x; 1.0255x over previous
#include <cuda_runtime.h>
#include <math.h>
#include <stdint.h>

// Problem constants (fixed by the reference)
#define BB    2
#define LL    1024
#define DM    1024
#define ED    2048
#define NS    16
#define DTR   64
#define TOK   (BB*LL)          // 2048 tokens
#define DBCW  128              // padded dbc row width (dt_rank 64 + B 16 + C 16 -> pad 128)

// -------- fp32 scratch --------
__device__ float    g_xz[(size_t)TOK * 2 * ED];     // in_proj output [tok][4096]
__device__ float    g_xc[(size_t)TOK * ED];         // conv+silu output (fp32, for scan)
__device__ float    g_dbc[(size_t)TOK * DBCW];      // x_proj output fp32 (for scan B/C)
__device__ float    g_delta[(size_t)TOK * ED];      // softplus(dt_proj) (for scan)
// -------- tf32 scratch (uint32 bit patterns) --------
__device__ uint32_t g_xt[(size_t)TOK * DM];         // x converted
__device__ uint32_t g_wt_in[(size_t)DM * 2 * ED];   // in_proj_w tf32
__device__ uint32_t g_wt_xp[(size_t)ED * DBCW];     // x_proj_w tf32, zero-padded to 128 cols
__device__ uint32_t g_wt_dt[(size_t)DTR * ED];      // dt_proj_w tf32
__device__ uint32_t g_wt_out[(size_t)ED * DM];      // out_proj_w tf32
__device__ uint32_t g_xct[(size_t)TOK * ED];        // xc tf32 (for xproj GEMM A)
__device__ uint32_t g_dbct[(size_t)TOK * DBCW];     // dbc tf32 (for dt GEMM A)
__device__ uint32_t g_yt[(size_t)TOK * ED];         // scan output tf32 (for out_proj A)

__device__ __forceinline__ uint32_t f2tf32(float f) {
    uint32_t u;
    asm("cvt.rna.tf32.f32 %0, %1;" : "=r"(u) : "f"(f));
    return u;
}

// ============================================================================
// prep: convert all GEMM operands that exist at launch time to tf32.
// seg0 in_proj_w | seg1 x | seg2 dt_proj_w | seg3 out_proj_w | seg4 x_proj_w(pad)
// ============================================================================
#define S0 (DM * 2 * ED)        // 4194304
#define S1 (TOK * DM)           // 2097152
#define S2 (DTR * ED)           // 131072
#define S3 (ED * DM)            // 2097152
#define S4 (ED * DBCW)          // 262144
#define STOT (S0 + S1 + S2 + S3 + S4)

__global__ void prep_kernel(const float* __restrict__ w_in,
                            const float* __restrict__ x,
                            const float* __restrict__ w_dt,
                            const float* __restrict__ w_out,
                            const float* __restrict__ w_xp)
{
    for (int i = blockIdx.x * blockDim.x + threadIdx.x; i < STOT;
         i += gridDim.x * blockDim.x) {
        int j = i;
        if (j < S0) { g_wt_in[j] = f2tf32(w_in[j]); continue; }
        j -= S0;
        if (j < S1) { g_xt[j] = f2tf32(x[j]); continue; }
        j -= S1;
        if (j < S2) { g_wt_dt[j] = f2tf32(w_dt[j]); continue; }
        j -= S2;
        if (j < S3) { g_wt_out[j] = f2tf32(w_out[j]); continue; }
        j -= S3;
        {   // x_proj_w: [ED][96] -> [ED][128] zero padded
            int r = j >> 7, c = j & 127;
            g_wt_xp[j] = (c < 96) ? f2tf32(w_xp[r * 96 + c]) : 0u;
        }
    }
}

// ============================================================================
// TF32 GEMM v2: inputs pre-converted tf32 (uint32). 128x128 tile, BK=16,
// 256 threads / 8 warps, warp tile 64x32, cp.async double buffer,
// conflict-free smem (A m-major pad 20, B k-major pad 136).
// EPI: 0 = store fp32 C; 1 = +bias[col] + softplus -> C; 2 = C fp32 + Ct tf32.
// ============================================================================
#define APAD 20
#define BPAD 136

__device__ __forceinline__ void cpa16(uint32_t dst, const void* src) {
    asm volatile("cp.async.cg.shared.global [%0], [%1], 16;\n"
                 :: "r"(dst), "l"(src));
}
__device__ __forceinline__ void cpa_commit() {
    asm volatile("cp.async.commit_group;\n");
}
template<int N>
__device__ __forceinline__ void cpa_wait() {
    asm volatile("cp.async.wait_group %0;\n" :: "n"(N));
}

template<int EPI>
__global__ void __launch_bounds__(256)
gemm_tf32(const uint32_t* __restrict__ A, const uint32_t* __restrict__ B,
          float* __restrict__ C, uint32_t* __restrict__ Ct,
          int M, int N, int K, int lda, int ldb, int ldc,
          const float* __restrict__ bias)
{
    __shared__ __align__(16) uint32_t As[2][128 * APAD];
    __shared__ __align__(16) uint32_t Bs[2][16 * BPAD];

    const int tid  = threadIdx.x;
    const int lane = tid & 31;
    const int wid  = tid >> 5;
    const int lm   = lane >> 2;   // 0..7
    const int lk   = lane & 3;    // 0..3

    const int bm = blockIdx.y * 128;
    const int bn = blockIdx.x * 128;
    const int wm = (wid >> 2) * 64;
    const int wn = (wid & 3) * 32;

    // cp.async geometry: A 512 chunks (row=c>>2, kc=(c&3)*4); B 512 (row=c>>5, nc=(c&31)*4)
    const int ac0r = tid >> 2,          ac0k = (tid & 3) << 2;
    const int ac1r = (tid + 256) >> 2,  ac1k = ac0k;
    const int bc0r = tid >> 5,          bc0n = (tid & 31) << 2;
    const int bc1r = bc0r + 8;

    const uint32_t* Ap0 = A + (size_t)(bm + ac0r) * lda + ac0k;
    const uint32_t* Ap1 = A + (size_t)(bm + ac1r) * lda + ac1k;
    const uint32_t* Bp0 = B + (size_t)bc0r * ldb + bn + bc0n;
    const uint32_t* Bp1 = B + (size_t)bc1r * ldb + bn + bc0n;

    uint32_t sA0[2], sA1[2], sB0[2], sB1[2];
#pragma unroll
    for (int s = 0; s < 2; ++s) {
        sA0[s] = (uint32_t)__cvta_generic_to_shared(&As[s][ac0r * APAD + ac0k]);
        sA1[s] = (uint32_t)__cvta_generic_to_shared(&As[s][ac1r * APAD + ac1k]);
        sB0[s] = (uint32_t)__cvta_generic_to_shared(&Bs[s][bc0r * BPAD + bc0n]);
        sB1[s] = (uint32_t)__cvta_generic_to_shared(&Bs[s][bc1r * BPAD + bc0n]);
    }

    float acc[4][4][4];
#pragma unroll
    for (int i = 0; i < 4; ++i)
#pragma unroll
        for (int j = 0; j < 4; ++j)
#pragma unroll
            for (int r = 0; r < 4; ++r) acc[i][j][r] = 0.f;

    const int KT = K / 16;

    // prologue: stage tile 0 into buffer 0
    cpa16(sA0[0], Ap0);
    cpa16(sA1[0], Ap1);
    cpa16(sB0[0], Bp0);
    cpa16(sB1[0], Bp1);
    cpa_commit();

    int buf = 0;
    for (int kt = 0; kt < KT; ++kt) {
        const bool has_next = (kt + 1 < KT);
        if (has_next) {
            int nb = buf ^ 1;
            int ko = (kt + 1) * 16;
            cpa16(sA0[nb], Ap0 + ko);
            cpa16(sA1[nb], Ap1 + ko);
            cpa16(sB0[nb], Bp0 + (size_t)ko * ldb);
            cpa16(sB1[nb], Bp1 + (size_t)ko * ldb);
            cpa_commit();
            cpa_wait<1>();
        } else {
            cpa_wait<0>();
        }
        __syncthreads();

        const uint32_t* Asb = As[buf];
        const uint32_t* Bsb = Bs[buf];
#pragma unroll
        for (int kb = 0; kb < 16; kb += 8) {
            uint32_t af[4][4], bf[4][2];
#pragma unroll
            for (int mt = 0; mt < 4; ++mt) {
                int m = wm + mt * 16 + lm;
                af[mt][0] = Asb[m * APAD + kb + lk];
                af[mt][1] = Asb[(m + 8) * APAD + kb + lk];
                af[mt][2] = Asb[m * APAD + kb + 4 + lk];
                af[mt][3] = Asb[(m + 8) * APAD + kb + 4 + lk];
            }
#pragma unroll
            for (int nt = 0; nt < 4; ++nt) {
                int n = wn + nt * 8 + lm;
                bf[nt][0] = Bsb[(kb + lk) * BPAD + n];
                bf[nt][1] = Bsb[(kb + 4 + lk) * BPAD + n];
            }
#pragma unroll
            for (int mt = 0; mt < 4; ++mt)
#pragma unroll
                for (int nt = 0; nt < 4; ++nt) {
                    asm volatile(
                        "mma.sync.aligned.m16n8k8.row.col.f32.tf32.tf32.f32 "
                        "{%0,%1,%2,%3}, {%4,%5,%6,%7}, {%8,%9}, {%0,%1,%2,%3};\n"
                        : "+f"(acc[mt][nt][0]), "+f"(acc[mt][nt][1]),
                          "+f"(acc[mt][nt][2]), "+f"(acc[mt][nt][3])
                        : "r"(af[mt][0]), "r"(af[mt][1]), "r"(af[mt][2]), "r"(af[mt][3]),
                          "r"(bf[nt][0]), "r"(bf[nt][1]));
                }
        }
        __syncthreads();
        buf ^= 1;
    }

    // epilogue
#pragma unroll
    for (int mt = 0; mt < 4; ++mt) {
#pragma unroll
        for (int nt = 0; nt < 4; ++nt) {
            int row = bm + wm + mt * 16 + lm;
            int col = bn + wn + nt * 8 + lk * 2;
            float v0 = acc[mt][nt][0], v1 = acc[mt][nt][1];
            float v2 = acc[mt][nt][2], v3 = acc[mt][nt][3];
            if (EPI == 1) {
                float bb0 = bias[col], bb1 = bias[col + 1];
                v0 += bb0; v1 += bb1; v2 += bb0; v3 += bb1;
                v0 = (v0 > 20.f) ? v0 : log1pf(expf(v0));
                v1 = (v1 > 20.f) ? v1 : log1pf(expf(v1));
                v2 = (v2 > 20.f) ? v2 : log1pf(expf(v2));
                v3 = (v3 > 20.f) ? v3 : log1pf(expf(v3));
            }
            *(float2*)(C + (size_t)row * ldc + col)       = make_float2(v0, v1);
            *(float2*)(C + (size_t)(row + 8) * ldc + col) = make_float2(v2, v3);
            if (EPI == 2) {
                uint32_t* cp0 = Ct + (size_t)row * ldc + col;
                uint32_t* cp1 = Ct + (size_t)(row + 8) * ldc + col;
                cp0[0] = f2tf32(v0); cp0[1] = f2tf32(v1);
                cp1[0] = f2tf32(v2); cp1[1] = f2tf32(v3);
            }
        }
    }
}

// ============================================================================
// Depthwise causal conv1d (k=4, left pad 3) + bias + SiLU.
// Writes fp32 (scan) AND tf32 (xproj GEMM A).
// ============================================================================
__global__ void conv_silu_kernel(const float* __restrict__ cw,
                                 const float* __restrict__ cb)
{
    int idx = blockIdx.x * blockDim.x + threadIdx.x;
    if (idx >= TOK * ED) return;
    int e = idx & (ED - 1);
    int t = idx >> 11;
    int l = t & (LL - 1);

    float w0 = cw[e * 4 + 0], w1 = cw[e * 4 + 1];
    float w2 = cw[e * 4 + 2], w3 = cw[e * 4 + 3];

    const float* col = g_xz + (size_t)t * (2 * ED) + e;
    float acc = cb[e] + w3 * col[0];
    if (l >= 1) acc = fmaf(w2, col[-(2 * ED)],     acc);
    if (l >= 2) acc = fmaf(w1, col[-2 * (2 * ED)], acc);
    if (l >= 3) acc = fmaf(w0, col[-3 * (2 * ED)], acc);

    float v = acc / (1.f + __expf(-acc));  // silu
    g_xc[idx]  = v;
    g_xct[idx] = f2tf32(v);
}

// ============================================================================
// Selective scan. One 16-lane group per (b, ed) chain; lane = state index n.
// Writes y as tf32 (only consumer is out_proj GEMM).
// ============================================================================
__global__ void __launch_bounds__(256)
scan_kernel(const float* __restrict__ A_log, const float* __restrict__ Dvec)
{
    const int tid  = threadIdx.x;
    const int g    = blockIdx.x * 16 + (tid >> 4);
    const int lane = tid & 15;
    const int b    = g >> 11;
    const int ed   = g & (ED - 1);

    const float An = -__expf(A_log[ed * NS + lane]);
    const float Dv = Dvec[ed];

    const float* dptr  = g_delta + (size_t)(b * LL) * ED + ed;
    const float* xptr  = g_xc    + (size_t)(b * LL) * ED + ed;
    const float* zptr  = g_xz    + (size_t)(b * LL) * (2 * ED) + ED + ed;
    const float* bcptr = g_dbc   + (size_t)(b * LL) * DBCW + DTR + lane;
    uint32_t*    yptr  = g_yt    + (size_t)(b * LL) * ED + ed;

    float h = 0.f;
#pragma unroll 4
    for (int l = 0; l < LL; ++l) {
        float dv = __ldg(dptr);
        float xv = __ldg(xptr);
        float Bv = __ldg(bcptr);
        float Cv = __ldg(bcptr + NS);

        float da = __expf(dv * An);
        h = fmaf(da, h, dv * Bv * xv);

        float p = h * Cv;
        p += __shfl_xor_sync(0xffffffffu, p, 1);
        p += __shfl_xor_sync(0xffffffffu, p, 2);
        p += __shfl_xor_sync(0xffffffffu, p, 4);
        p += __shfl_xor_sync(0xffffffffu, p, 8);

        if (lane == 0) {
            float zv = __ldg(zptr);
            float s  = zv / (1.f + __expf(-zv));
            *yptr = f2tf32((p + Dv * xv) * s);
        }
        dptr  += ED;
        xptr  += ED;
        zptr  += 2 * ED;
        bcptr += DBCW;
        yptr  += ED;
    }
}

// ============================================================================
extern "C" void kernel_launch(void* const* d_in, const int* in_sizes, int n_in,
                              void* d_out, int out_size)
{
    const float* x         = (const float*)d_in[0];
    const float* in_proj_w = (const float*)d_in[1];
    const float* conv_w    = (const float*)d_in[2];
    const float* conv_b    = (const float*)d_in[3];
    const float* x_proj_w  = (const float*)d_in[4];
    const float* dt_proj_w = (const float*)d_in[5];
    const float* dt_proj_b = (const float*)d_in[6];
    const float* A_log     = (const float*)d_in[7];
    const float* Dvec      = (const float*)d_in[8];
    const float* out_proj_w= (const float*)d_in[9];
    float* out = (float*)d_out;

    static float    *p_xz = nullptr, *p_dbc = nullptr, *p_delta = nullptr;
    static uint32_t *p_xt, *p_win, *p_wxp, *p_wdt, *p_wout, *p_xct, *p_dbct, *p_yt;
    if (!p_xz) {
        cudaGetSymbolAddress((void**)&p_xz,    g_xz);
        cudaGetSymbolAddress((void**)&p_dbc,   g_dbc);
        cudaGetSymbolAddress((void**)&p_delta, g_delta);
        cudaGetSymbolAddress((void**)&p_xt,    g_xt);
        cudaGetSymbolAddress((void**)&p_win,   g_wt_in);
        cudaGetSymbolAddress((void**)&p_wxp,   g_wt_xp);
        cudaGetSymbolAddress((void**)&p_wdt,   g_wt_dt);
        cudaGetSymbolAddress((void**)&p_wout,  g_wt_out);
        cudaGetSymbolAddress((void**)&p_xct,   g_xct);
        cudaGetSymbolAddress((void**)&p_dbct,  g_dbct);
        cudaGetSymbolAddress((void**)&p_yt,    g_yt);
    }

    // [0] convert weights + x to tf32
    prep_kernel<<<4096, 256>>>(in_proj_w, x, dt_proj_w, out_proj_w, x_proj_w);

    // [1] xz = x @ in_proj_w : (2048x1024)@(1024x4096) -> fp32
    gemm_tf32<0><<<dim3(2 * ED / 128, TOK / 128), 256>>>(
        p_xt, p_win, p_xz, nullptr, TOK, 2 * ED, DM, DM, 2 * ED, 2 * ED, nullptr);

    // [2] depthwise causal conv + silu -> xc (fp32 + tf32)
    conv_silu_kernel<<<(TOK * ED + 255) / 256, 256>>>(conv_w, conv_b);

    // [3] dbc = xc @ x_proj_w(padded) : (2048x2048)@(2048x128) -> fp32 + tf32
    gemm_tf32<2><<<dim3(1, TOK / 128), 256>>>(
        p_xct, p_wxp, p_dbc, p_dbct, TOK, DBCW, ED, ED, DBCW, DBCW, nullptr);

    // [4] delta = softplus(dbc[:, :64] @ dt_proj_w + b) : (2048x64)@(64x2048)
    gemm_tf32<1><<<dim3(ED / 128, TOK / 128), 256>>>(
        p_dbct, p_wdt, p_delta, nullptr, TOK, ED, DTR, DBCW, ED, ED, dt_proj_b);

    // [5] selective scan -> y (tf32)
    scan_kernel<<<(BB * ED) / 16, 256>>>(A_log, Dvec);

    // [6] out = y @ out_proj_w : (2048x2048)@(2048x1024)
    gemm_tf32<0><<<dim3(DM / 128, TOK / 128), 256>>>(
        p_yt, p_wout, out, nullptr, TOK, DM, ED, ED, DM, DM, nullptr);
}

// round 4
// speedup vs baseline: 2.4565x; 1.7492x over previous
#include <cuda_runtime.h>
#include <math.h>
#include <stdint.h>

// Problem constants (fixed by the reference)
#define BB    2
#define LL    1024
#define DM    1024
#define ED    2048
#define NS    16
#define DTR   64
#define TOK   (BB*LL)          // 2048 tokens
#define DBCW  128              // padded dbc row width (64 dt + 16 B + 16 C + pad)
#define KSPL  8                // split-K factor for xproj
#define KCH   (ED / KSPL)      // 256

// -------- fp32 scratch --------
__device__ float    g_xz[(size_t)TOK * 2 * ED];
__device__ float    g_xc[(size_t)TOK * ED];
__device__ float    g_dbc[(size_t)TOK * DBCW];
__device__ float    g_delta[(size_t)TOK * ED];
__device__ float    g_part[(size_t)KSPL * TOK * DBCW];   // split-K partials (8 MB)
// -------- tf32 scratch --------
__device__ uint32_t g_xt[(size_t)TOK * DM];
__device__ uint32_t g_wt_in[(size_t)DM * 2 * ED];
__device__ uint32_t g_wt_xp[(size_t)ED * DBCW];
__device__ uint32_t g_wt_dt[(size_t)DTR * ED];
__device__ uint32_t g_wt_out[(size_t)ED * DM];
__device__ uint32_t g_xct[(size_t)TOK * ED];
__device__ uint32_t g_dbct[(size_t)TOK * DBCW];
__device__ uint32_t g_yt[(size_t)TOK * ED];

__device__ __forceinline__ uint32_t f2tf32(float f) {
    uint32_t u;
    asm("cvt.rna.tf32.f32 %0, %1;" : "=r"(u) : "f"(f));
    return u;
}

// ============================================================================
// prep kernels (3 separate launches so the 4th launch = in_proj for profiling)
// ============================================================================
__global__ void prep_w1(const float* __restrict__ w_in)
{
    for (int i = blockIdx.x * blockDim.x + threadIdx.x; i < DM * 2 * ED;
         i += gridDim.x * blockDim.x)
        g_wt_in[i] = f2tf32(w_in[i]);
}

#define P2A (DTR * ED)
#define P2B (ED * DM)
#define P2C (ED * DBCW)
__global__ void prep_w2(const float* __restrict__ w_dt,
                        const float* __restrict__ w_out,
                        const float* __restrict__ w_xp)
{
    for (int i = blockIdx.x * blockDim.x + threadIdx.x; i < P2A + P2B + P2C;
         i += gridDim.x * blockDim.x) {
        int j = i;
        if (j < P2A) { g_wt_dt[j] = f2tf32(w_dt[j]); continue; }
        j -= P2A;
        if (j < P2B) { g_wt_out[j] = f2tf32(w_out[j]); continue; }
        j -= P2B;
        int r = j >> 7, c = j & 127;
        g_wt_xp[j] = (c < 96) ? f2tf32(w_xp[r * 96 + c]) : 0u;
    }
}

__global__ void prep_x(const float* __restrict__ x)
{
    for (int i = blockIdx.x * blockDim.x + threadIdx.x; i < TOK * DM;
         i += gridDim.x * blockDim.x)
        g_xt[i] = f2tf32(x[i]);
}

// ============================================================================
// TF32 GEMM v3: 128x128 tile, BK=16, 256 threads / 8 warps, warp tile 64x32,
// 4-stage cp.async pipeline, one __syncthreads per k-tile, zfill tail.
// A pre-converted tf32 [M][K] row-major, B tf32 [K][N] row-major.
// EPI: 0 = fp32 C; 1 = +bias + softplus; 3 = split-K partial (blockIdx.z).
// ============================================================================
#define STAGES 4
#define APAD 20
#define BPAD 136
#define ASMSZ (128 * APAD)     // uint32 per stage
#define BSMSZ (16 * BPAD)
#define GEMM_SMEM (STAGES * (ASMSZ + BSMSZ) * 4)

__device__ __forceinline__ void cpa16z(uint32_t dst, const void* src, bool valid) {
    int sz = valid ? 16 : 0;
    asm volatile("cp.async.cg.shared.global [%0], [%1], 16, %2;\n"
                 :: "r"(dst), "l"(src), "r"(sz));
}
__device__ __forceinline__ void cpa_commit() {
    asm volatile("cp.async.commit_group;\n");
}
template<int N>
__device__ __forceinline__ void cpa_wait() {
    asm volatile("cp.async.wait_group %0;\n" :: "n"(N));
}

template<int EPI>
__global__ void __launch_bounds__(256)
gemm_tf32(const uint32_t* __restrict__ A, const uint32_t* __restrict__ B,
          float* __restrict__ C, int M, int N, int K,
          int lda, int ldb, int ldc, const float* __restrict__ bias)
{
    extern __shared__ __align__(16) uint32_t smem_u[];
    uint32_t* As = smem_u;                     // STAGES * ASMSZ
    uint32_t* Bs = smem_u + STAGES * ASMSZ;    // STAGES * BSMSZ

    if (EPI == 3) {
        A += (size_t)blockIdx.z * K;               // K = chunk length
        B += (size_t)blockIdx.z * K * ldb;
        C += (size_t)blockIdx.z * M * ldc;
    }

    const int tid  = threadIdx.x;
    const int lane = tid & 31;
    const int wid  = tid >> 5;
    const int lm   = lane >> 2;
    const int lk   = lane & 3;

    const int bm = blockIdx.y * 128;
    const int bn = blockIdx.x * 128;
    const int wm = (wid >> 2) * 64;
    const int wn = (wid & 3) * 32;

    const int ac0r = tid >> 2,         ac0k = (tid & 3) << 2;
    const int ac1r = (tid + 256) >> 2;
    const int bc0r = tid >> 5,         bc0n = (tid & 31) << 2;
    const int bc1r = bc0r + 8;

    const uint32_t* Ap0 = A + (size_t)(bm + ac0r) * lda + ac0k;
    const uint32_t* Ap1 = A + (size_t)(bm + ac1r) * lda + ac0k;
    const uint32_t* Bp0 = B + (size_t)bc0r * ldb + bn + bc0n;
    const uint32_t* Bp1 = B + (size_t)bc1r * ldb + bn + bc0n;

    const uint32_t sAb = (uint32_t)__cvta_generic_to_shared(As);
    const uint32_t sBb = (uint32_t)__cvta_generic_to_shared(Bs);
    const uint32_t oA0 = (ac0r * APAD + ac0k) * 4;
    const uint32_t oA1 = (ac1r * APAD + ac0k) * 4;
    const uint32_t oB0 = (bc0r * BPAD + bc0n) * 4;
    const uint32_t oB1 = (bc1r * BPAD + bc0n) * 4;

    const int KT = K / 16;

    float acc[4][4][4];
#pragma unroll
    for (int i = 0; i < 4; ++i)
#pragma unroll
        for (int j = 0; j < 4; ++j)
#pragma unroll
            for (int r = 0; r < 4; ++r) acc[i][j][r] = 0.f;

    // stage issue helper (zfill beyond KT keeps group accounting uniform)
    auto issue = [&](int kt) {
        bool v = kt < KT;
        int st = kt & (STAGES - 1);
        int ko = kt * 16;
        cpa16z(sAb + st * (ASMSZ * 4) + oA0, Ap0 + ko, v);
        cpa16z(sAb + st * (ASMSZ * 4) + oA1, Ap1 + ko, v);
        cpa16z(sBb + st * (BSMSZ * 4) + oB0, Bp0 + (size_t)ko * ldb, v);
        cpa16z(sBb + st * (BSMSZ * 4) + oB1, Bp1 + (size_t)ko * ldb, v);
        cpa_commit();
    };

    // prologue: tiles 0..2
    issue(0); issue(1); issue(2);

    for (int kt = 0; kt < KT; ++kt) {
        cpa_wait<STAGES - 2>();     // tile kt landed
        __syncthreads();            // visible to all; all warps done with buf (kt+3)%4
        issue(kt + STAGES - 1);     // overwrite buf (kt-1)%4 — safe after barrier

        const uint32_t* Asb = As + (kt & (STAGES - 1)) * ASMSZ;
        const uint32_t* Bsb = Bs + (kt & (STAGES - 1)) * BSMSZ;
#pragma unroll
        for (int kb = 0; kb < 16; kb += 8) {
            uint32_t af[4][4], bf[4][2];
#pragma unroll
            for (int mt = 0; mt < 4; ++mt) {
                int m = wm + mt * 16 + lm;
                af[mt][0] = Asb[m * APAD + kb + lk];
                af[mt][1] = Asb[(m + 8) * APAD + kb + lk];
                af[mt][2] = Asb[m * APAD + kb + 4 + lk];
                af[mt][3] = Asb[(m + 8) * APAD + kb + 4 + lk];
            }
#pragma unroll
            for (int nt = 0; nt < 4; ++nt) {
                int n = wn + nt * 8 + lm;
                bf[nt][0] = Bsb[(kb + lk) * BPAD + n];
                bf[nt][1] = Bsb[(kb + 4 + lk) * BPAD + n];
            }
#pragma unroll
            for (int mt = 0; mt < 4; ++mt)
#pragma unroll
                for (int nt = 0; nt < 4; ++nt) {
                    asm volatile(
                        "mma.sync.aligned.m16n8k8.row.col.f32.tf32.tf32.f32 "
                        "{%0,%1,%2,%3}, {%4,%5,%6,%7}, {%8,%9}, {%0,%1,%2,%3};\n"
                        : "+f"(acc[mt][nt][0]), "+f"(acc[mt][nt][1]),
                          "+f"(acc[mt][nt][2]), "+f"(acc[mt][nt][3])
                        : "r"(af[mt][0]), "r"(af[mt][1]), "r"(af[mt][2]), "r"(af[mt][3]),
                          "r"(bf[nt][0]), "r"(bf[nt][1]));
                }
        }
    }

    // epilogue
#pragma unroll
    for (int mt = 0; mt < 4; ++mt) {
#pragma unroll
        for (int nt = 0; nt < 4; ++nt) {
            int row = bm + wm + mt * 16 + lm;
            int col = bn + wn + nt * 8 + lk * 2;
            float v0 = acc[mt][nt][0], v1 = acc[mt][nt][1];
            float v2 = acc[mt][nt][2], v3 = acc[mt][nt][3];
            if (EPI == 1) {
                float bb0 = bias[col], bb1 = bias[col + 1];
                v0 += bb0; v1 += bb1; v2 += bb0; v3 += bb1;
                v0 = (v0 > 20.f) ? v0 : log1pf(expf(v0));
                v1 = (v1 > 20.f) ? v1 : log1pf(expf(v1));
                v2 = (v2 > 20.f) ? v2 : log1pf(expf(v2));
                v3 = (v3 > 20.f) ? v3 : log1pf(expf(v3));
            }
            *(float2*)(C + (size_t)row * ldc + col)       = make_float2(v0, v1);
            *(float2*)(C + (size_t)(row + 8) * ldc + col) = make_float2(v2, v3);
        }
    }
}

// ============================================================================
// split-K reduce for xproj: sum 8 partials -> g_dbc (fp32) + g_dbct (tf32)
// ============================================================================
__global__ void reduce_dbc()
{
    int i = blockIdx.x * blockDim.x + threadIdx.x;   // over float4s
    if (i >= TOK * DBCW / 4) return;
    const float4* p = (const float4*)g_part;
    float4 s = p[i];
#pragma unroll
    for (int k = 1; k < KSPL; ++k) {
        float4 t = p[(size_t)k * (TOK * DBCW / 4) + i];
        s.x += t.x; s.y += t.y; s.z += t.z; s.w += t.w;
    }
    ((float4*)g_dbc)[i] = s;
    uint4 u = make_uint4(f2tf32(s.x), f2tf32(s.y), f2tf32(s.z), f2tf32(s.w));
    ((uint4*)g_dbct)[i] = u;
}

// ============================================================================
// Depthwise causal conv1d (k=4) + bias + SiLU -> xc (fp32 + tf32)
// ============================================================================
__global__ void conv_silu_kernel(const float* __restrict__ cw,
                                 const float* __restrict__ cb)
{
    int idx = blockIdx.x * blockDim.x + threadIdx.x;
    if (idx >= TOK * ED) return;
    int e = idx & (ED - 1);
    int t = idx >> 11;
    int l = t & (LL - 1);

    float w0 = cw[e * 4 + 0], w1 = cw[e * 4 + 1];
    float w2 = cw[e * 4 + 2], w3 = cw[e * 4 + 3];

    const float* col = g_xz + (size_t)t * (2 * ED) + e;
    float acc = cb[e] + w3 * col[0];
    if (l >= 1) acc = fmaf(w2, col[-(2 * ED)],     acc);
    if (l >= 2) acc = fmaf(w1, col[-2 * (2 * ED)], acc);
    if (l >= 3) acc = fmaf(w0, col[-3 * (2 * ED)], acc);

    float v = acc / (1.f + __expf(-acc));
    g_xc[idx]  = v;
    g_xct[idx] = f2tf32(v);
}

// ============================================================================
// Selective scan, 4-step batched for ILP. 16-lane group per (b, ed) chain.
// ============================================================================
__global__ void __launch_bounds__(256)
scan_kernel(const float* __restrict__ A_log, const float* __restrict__ Dvec)
{
    const int tid  = threadIdx.x;
    const int g    = blockIdx.x * 16 + (tid >> 4);
    const int lane = tid & 15;
    const int b    = g >> 11;
    const int ed   = g & (ED - 1);

    const float An = -__expf(A_log[ed * NS + lane]);
    const float Dv = Dvec[ed];

    const float* dptr  = g_delta + (size_t)(b * LL) * ED + ed;
    const float* xptr  = g_xc    + (size_t)(b * LL) * ED + ed;
    const float* zptr  = g_xz    + (size_t)(b * LL) * (2 * ED) + ED + ed;
    const float* bcptr = g_dbc   + (size_t)(b * LL) * DBCW + DTR + lane;
    uint32_t*    yptr  = g_yt    + (size_t)(b * LL) * ED + ed;

    float h = 0.f;
    for (int l0 = 0; l0 < LL; l0 += 4) {
        float dv[4], xv[4], bv[4], cv[4], zv;
#pragma unroll
        for (int j = 0; j < 4; ++j) {
            dv[j] = dptr[(size_t)j * ED];
            xv[j] = xptr[(size_t)j * ED];
            bv[j] = bcptr[(size_t)j * DBCW];
            cv[j] = bcptr[(size_t)j * DBCW + NS];
        }
        zv = zptr[(size_t)(lane & 3) * 2 * ED];   // step (lane&3)'s z

        // serial h-chain (only exp+fma on the critical path)
        float p0, p1, p2, p3;
        {
            float da;
            da = __expf(dv[0] * An); h = fmaf(da, h, dv[0] * bv[0] * xv[0]); p0 = h * cv[0];
            da = __expf(dv[1] * An); h = fmaf(da, h, dv[1] * bv[1] * xv[1]); p1 = h * cv[1];
            da = __expf(dv[2] * An); h = fmaf(da, h, dv[2] * bv[2] * xv[2]); p2 = h * cv[2];
            da = __expf(dv[3] * An); h = fmaf(da, h, dv[3] * bv[3] * xv[3]); p3 = h * cv[3];
        }

        // 4 interleaved butterfly reductions over the 16-lane group
#pragma unroll
        for (int m = 1; m < 16; m <<= 1) {
            p0 += __shfl_xor_sync(0xffffffffu, p0, m);
            p1 += __shfl_xor_sync(0xffffffffu, p1, m);
            p2 += __shfl_xor_sync(0xffffffffu, p2, m);
            p3 += __shfl_xor_sync(0xffffffffu, p3, m);
        }

        if (lane < 4) {
            float p = (lane == 0) ? p0 : (lane == 1) ? p1 : (lane == 2) ? p2 : p3;
            float xj = (lane == 0) ? xv[0] : (lane == 1) ? xv[1] : (lane == 2) ? xv[2] : xv[3];
            float s = zv / (1.f + __expf(-zv));
            yptr[(size_t)lane * ED] = f2tf32((p + Dv * xj) * s);
        }

        dptr  += 4 * ED;
        xptr  += 4 * ED;
        zptr  += 4 * 2 * ED;
        bcptr += 4 * DBCW;
        yptr  += 4 * ED;
    }
}

// ============================================================================
extern "C" void kernel_launch(void* const* d_in, const int* in_sizes, int n_in,
                              void* d_out, int out_size)
{
    const float* x         = (const float*)d_in[0];
    const float* in_proj_w = (const float*)d_in[1];
    const float* conv_w    = (const float*)d_in[2];
    const float* conv_b    = (const float*)d_in[3];
    const float* x_proj_w  = (const float*)d_in[4];
    const float* dt_proj_w = (const float*)d_in[5];
    const float* dt_proj_b = (const float*)d_in[6];
    const float* A_log     = (const float*)d_in[7];
    const float* Dvec      = (const float*)d_in[8];
    const float* out_proj_w= (const float*)d_in[9];
    float* out = (float*)d_out;

    static float    *p_xz = nullptr, *p_delta = nullptr, *p_part = nullptr;
    static uint32_t *p_xt, *p_win, *p_wxp, *p_wdt, *p_wout, *p_xct, *p_dbct, *p_yt;
    if (!p_xz) {
        cudaGetSymbolAddress((void**)&p_xz,    g_xz);
        cudaGetSymbolAddress((void**)&p_delta, g_delta);
        cudaGetSymbolAddress((void**)&p_part,  g_part);
        cudaGetSymbolAddress((void**)&p_xt,    g_xt);
        cudaGetSymbolAddress((void**)&p_win,   g_wt_in);
        cudaGetSymbolAddress((void**)&p_wxp,   g_wt_xp);
        cudaGetSymbolAddress((void**)&p_wdt,   g_wt_dt);
        cudaGetSymbolAddress((void**)&p_wout,  g_wt_out);
        cudaGetSymbolAddress((void**)&p_xct,   g_xct);
        cudaGetSymbolAddress((void**)&p_dbct,  g_dbct);
        cudaGetSymbolAddress((void**)&p_yt,    g_yt);
        cudaFuncSetAttribute(gemm_tf32<0>, cudaFuncAttributeMaxDynamicSharedMemorySize, GEMM_SMEM);
        cudaFuncSetAttribute(gemm_tf32<1>, cudaFuncAttributeMaxDynamicSharedMemorySize, GEMM_SMEM);
        cudaFuncSetAttribute(gemm_tf32<3>, cudaFuncAttributeMaxDynamicSharedMemorySize, GEMM_SMEM);
    }

    // [0-2] tf32 conversions (3 launches so launch #3 = in_proj is profiled)
    prep_w1<<<2048, 256>>>(in_proj_w);
    prep_w2<<<1024, 256>>>(dt_proj_w, out_proj_w, x_proj_w);
    prep_x <<<1024, 256>>>(x);

    // [3] xz = x @ in_proj_w : (2048x1024)@(1024x4096)
    gemm_tf32<0><<<dim3(2 * ED / 128, TOK / 128), 256, GEMM_SMEM>>>(
        p_xt, p_win, p_xz, TOK, 2 * ED, DM, DM, 2 * ED, 2 * ED, nullptr);

    // [4] depthwise causal conv + silu
    conv_silu_kernel<<<(TOK * ED + 255) / 256, 256>>>(conv_w, conv_b);

    // [5] dbc partials: split-K xproj (2048x2048)@(2048x128), 8 K-chunks
    gemm_tf32<3><<<dim3(1, TOK / 128, KSPL), 256, GEMM_SMEM>>>(
        p_xct, p_wxp, p_part, TOK, DBCW, KCH, ED, DBCW, DBCW, nullptr);

    // [6] reduce partials -> dbc fp32 + tf32
    reduce_dbc<<<(TOK * DBCW / 4 + 255) / 256, 256>>>();

    // [7] delta = softplus(dbc[:, :64] @ dt_proj_w + b)
    gemm_tf32<1><<<dim3(ED / 128, TOK / 128), 256, GEMM_SMEM>>>(
        p_dbct, p_wdt, p_delta, TOK, ED, DTR, DBCW, ED, ED, dt_proj_b);

    // [8] selective scan -> y (tf32)
    scan_kernel<<<(BB * ED) / 16, 256>>>(A_log, Dvec);

    // [9] out = y @ out_proj_w : (2048x2048)@(2048x1024)
    gemm_tf32<0><<<dim3(DM / 128, TOK / 128), 256, GEMM_SMEM>>>(
        p_yt, p_wout, out, TOK, DM, ED, ED, DM, DM, nullptr);
}

// round 7
// speedup vs baseline: 2.8041x; 1.1415x over previous
#include <cuda_runtime.h>
#include <math.h>
#include <stdint.h>

// Problem constants
#define BB    2
#define LL    1024
#define DM    1024
#define ED    2048
#define NS    16
#define DTR   64
#define TOK   (BB*LL)          // 2048
#define DBCW  128              // padded dbc width (64 dt + 16 B + 16 C + pad)
#define KSPL  8
#define KCH   (ED / KSPL)      // 256
#define OSPL  2                // split-K for out_proj

// -------- fp32 scratch --------
__device__ float    g_xz[(size_t)TOK * 2 * ED];
__device__ float    g_xc[(size_t)TOK * ED];
__device__ float    g_dbc[(size_t)TOK * DBCW];
__device__ float    g_delta[(size_t)TOK * ED];
__device__ float    g_part[(size_t)KSPL * TOK * DBCW];
__device__ float    g_opart[(size_t)OSPL * TOK * DM];
// -------- tf32 scratch --------
__device__ uint32_t g_xt[(size_t)TOK * DM];
__device__ uint32_t g_wt_in[(size_t)DM * 2 * ED];
__device__ uint32_t g_wt_xp[(size_t)ED * DBCW];
__device__ uint32_t g_wt_dt[(size_t)DTR * ED];
__device__ uint32_t g_wt_out[(size_t)ED * DM];
__device__ uint32_t g_xct[(size_t)TOK * ED];
__device__ uint32_t g_dbct[(size_t)TOK * DBCW];
__device__ uint32_t g_yt[(size_t)TOK * ED];

__device__ __forceinline__ uint32_t f2tf32(float f) {
    uint32_t u;
    asm("cvt.rna.tf32.f32 %0, %1;" : "=r"(u) : "f"(f));
    return u;
}

// ============================================================================
// prep kernels (3 launches so launch index 3 = in_proj GEMM for profiling)
// ============================================================================
__global__ void prep_w1(const float* __restrict__ w_in)
{
    for (int i = blockIdx.x * blockDim.x + threadIdx.x; i < DM * 2 * ED;
         i += gridDim.x * blockDim.x)
        g_wt_in[i] = f2tf32(w_in[i]);
}

#define P2A (DTR * ED)
#define P2B (ED * DM)
#define P2C (ED * DBCW)
__global__ void prep_w2(const float* __restrict__ w_dt,
                        const float* __restrict__ w_out,
                        const float* __restrict__ w_xp)
{
    for (int i = blockIdx.x * blockDim.x + threadIdx.x; i < P2A + P2B + P2C;
         i += gridDim.x * blockDim.x) {
        int j = i;
        if (j < P2A) { g_wt_dt[j] = f2tf32(w_dt[j]); continue; }
        j -= P2A;
        if (j < P2B) { g_wt_out[j] = f2tf32(w_out[j]); continue; }
        j -= P2B;
        int r = j >> 7, c = j & 127;
        g_wt_xp[j] = (c < 96) ? f2tf32(w_xp[r * 96 + c]) : 0u;
    }
}

__global__ void prep_x(const float* __restrict__ x)
{
    for (int i = blockIdx.x * blockDim.x + threadIdx.x; i < TOK * DM;
         i += gridDim.x * blockDim.x)
        g_xt[i] = f2tf32(x[i]);
}

// ============================================================================
// TF32 GEMM v4: 128x128 CTA tile, 128 threads / 4 warps, WARP TILE 64x64
// (32 MMAs per 32 LDS per k8 block — 2x better MMA:LDS than v3).
// BK=16, 4-stage cp.async pipeline, zfill tail.
// A tf32 [M][K] row-major, B tf32 [K][N] row-major.
// EPI: 0 = fp32 C; 1 = +bias + softplus; 3 = split-K partial (blockIdx.z).
// ============================================================================
#define STG  4
#define APAD 20
#define BPAD 136
#define ASMSZ (128 * APAD)
#define BSMSZ (16 * BPAD)
#define GEMM_SMEM (STG * (ASMSZ + BSMSZ) * 4)

__device__ __forceinline__ void cpa16z(uint32_t dst, const void* src, bool valid) {
    int sz = valid ? 16 : 0;
    asm volatile("cp.async.cg.shared.global [%0], [%1], 16, %2;\n"
                 :: "r"(dst), "l"(src), "r"(sz));
}
__device__ __forceinline__ void cpa_commit() {
    asm volatile("cp.async.commit_group;\n");
}
template<int N>
__device__ __forceinline__ void cpa_wait() {
    asm volatile("cp.async.wait_group %0;\n" :: "n"(N));
}

template<int EPI>
__global__ void __launch_bounds__(128)
gemm_tf32(const uint32_t* __restrict__ A, const uint32_t* __restrict__ B,
          float* __restrict__ C, int M, int N, int K,
          int lda, int ldb, int ldc, const float* __restrict__ bias)
{
    extern __shared__ __align__(16) uint32_t smem_u[];
    uint32_t* As = smem_u;
    uint32_t* Bs = smem_u + STG * ASMSZ;

    if (EPI == 3) {
        A += (size_t)blockIdx.z * K;           // K = chunk length
        B += (size_t)blockIdx.z * K * ldb;
        C += (size_t)blockIdx.z * M * ldc;
    }

    const int tid  = threadIdx.x;
    const int lane = tid & 31;
    const int wid  = tid >> 5;
    const int lm   = lane >> 2;    // 0..7
    const int lk   = lane & 3;     // 0..3

    const int bm = blockIdx.y * 128;
    const int bn = blockIdx.x * 128;
    const int wm = (wid >> 1) * 64;    // 0 or 64
    const int wn = (wid & 1) * 64;     // 0 or 64

    // cp.async geometry: per thread 4 A chunks + 4 B chunks (16B each)
    uint32_t oA[4], oB[4];
    const uint32_t *Ag[4], *Bg[4];
#pragma unroll
    for (int t = 0; t < 4; ++t) {
        int ia = tid + 128 * t;            // 0..511
        int ar = ia >> 2, ak = (ia & 3) << 2;
        oA[t] = (uint32_t)(ar * APAD + ak) * 4;
        Ag[t] = A + (size_t)(bm + ar) * lda + ak;
        int br = ia >> 5, bc = (ia & 31) << 2;
        oB[t] = (uint32_t)(br * BPAD + bc) * 4;
        Bg[t] = B + (size_t)br * ldb + bn + bc;
    }
    const uint32_t sAb = (uint32_t)__cvta_generic_to_shared(As);
    const uint32_t sBb = (uint32_t)__cvta_generic_to_shared(Bs);

    const int KT = K / 16;

    float acc[4][8][4];
#pragma unroll
    for (int i = 0; i < 4; ++i)
#pragma unroll
        for (int j = 0; j < 8; ++j)
#pragma unroll
            for (int r = 0; r < 4; ++r) acc[i][j][r] = 0.f;

    auto issue = [&](int kt) {
        bool v = kt < KT;
        int st = kt & (STG - 1);
        int ko = kt * 16;
        uint32_t ab = sAb + st * (ASMSZ * 4);
        uint32_t bb = sBb + st * (BSMSZ * 4);
#pragma unroll
        for (int t = 0; t < 4; ++t) cpa16z(ab + oA[t], Ag[t] + ko, v);
#pragma unroll
        for (int t = 0; t < 4; ++t) cpa16z(bb + oB[t], Bg[t] + (size_t)ko * ldb, v);
        cpa_commit();
    };

    issue(0); issue(1); issue(2);

    for (int kt = 0; kt < KT; ++kt) {
        cpa_wait<STG - 2>();
        __syncthreads();
        issue(kt + STG - 1);

        const uint32_t* Asb = As + (kt & (STG - 1)) * ASMSZ;
        const uint32_t* Bsb = Bs + (kt & (STG - 1)) * BSMSZ;
#pragma unroll
        for (int kb = 0; kb < 16; kb += 8) {
            uint32_t af[4][4], bf[8][2];
#pragma unroll
            for (int mt = 0; mt < 4; ++mt) {
                int m = wm + mt * 16 + lm;
                af[mt][0] = Asb[m * APAD + kb + lk];
                af[mt][1] = Asb[(m + 8) * APAD + kb + lk];
                af[mt][2] = Asb[m * APAD + kb + 4 + lk];
                af[mt][3] = Asb[(m + 8) * APAD + kb + 4 + lk];
            }
#pragma unroll
            for (int nt = 0; nt < 8; ++nt) {
                int n = wn + nt * 8 + lm;
                bf[nt][0] = Bsb[(kb + lk) * BPAD + n];
                bf[nt][1] = Bsb[(kb + 4 + lk) * BPAD + n];
            }
#pragma unroll
            for (int mt = 0; mt < 4; ++mt)
#pragma unroll
                for (int nt = 0; nt < 8; ++nt) {
                    asm volatile(
                        "mma.sync.aligned.m16n8k8.row.col.f32.tf32.tf32.f32 "
                        "{%0,%1,%2,%3}, {%4,%5,%6,%7}, {%8,%9}, {%0,%1,%2,%3};\n"
                        : "+f"(acc[mt][nt][0]), "+f"(acc[mt][nt][1]),
                          "+f"(acc[mt][nt][2]), "+f"(acc[mt][nt][3])
                        : "r"(af[mt][0]), "r"(af[mt][1]), "r"(af[mt][2]), "r"(af[mt][3]),
                          "r"(bf[nt][0]), "r"(bf[nt][1]));
                }
        }
    }

    // epilogue
#pragma unroll
    for (int mt = 0; mt < 4; ++mt) {
#pragma unroll
        for (int nt = 0; nt < 8; ++nt) {
            int row = bm + wm + mt * 16 + lm;
            int col = bn + wn + nt * 8 + lk * 2;
            float v0 = acc[mt][nt][0], v1 = acc[mt][nt][1];
            float v2 = acc[mt][nt][2], v3 = acc[mt][nt][3];
            if (EPI == 1) {
                float bb0 = bias[col], bb1 = bias[col + 1];
                v0 += bb0; v1 += bb1; v2 += bb0; v3 += bb1;
                v0 = (v0 > 20.f) ? v0 : log1pf(expf(v0));
                v1 = (v1 > 20.f) ? v1 : log1pf(expf(v1));
                v2 = (v2 > 20.f) ? v2 : log1pf(expf(v2));
                v3 = (v3 > 20.f) ? v3 : log1pf(expf(v3));
            }
            *(float2*)(C + (size_t)row * ldc + col)       = make_float2(v0, v1);
            *(float2*)(C + (size_t)(row + 8) * ldc + col) = make_float2(v2, v3);
        }
    }
}

// ============================================================================
// split-K reduces
// ============================================================================
__global__ void reduce_dbc()
{
    int i = blockIdx.x * blockDim.x + threadIdx.x;
    if (i >= TOK * DBCW / 4) return;
    const float4* p = (const float4*)g_part;
    float4 s = p[i];
#pragma unroll
    for (int k = 1; k < KSPL; ++k) {
        float4 t = p[(size_t)k * (TOK * DBCW / 4) + i];
        s.x += t.x; s.y += t.y; s.z += t.z; s.w += t.w;
    }
    ((float4*)g_dbc)[i] = s;
    ((uint4*)g_dbct)[i] = make_uint4(f2tf32(s.x), f2tf32(s.y), f2tf32(s.z), f2tf32(s.w));
}

__global__ void reduce_out(float* __restrict__ out)
{
    int i = blockIdx.x * blockDim.x + threadIdx.x;
    if (i >= TOK * DM / 4) return;
    const float4* p = (const float4*)g_opart;
    float4 a = p[i];
    float4 b = p[(size_t)(TOK * DM / 4) + i];
    ((float4*)out)[i] = make_float4(a.x + b.x, a.y + b.y, a.z + b.z, a.w + b.w);
}

// ============================================================================
// Depthwise causal conv1d (k=4) + bias + SiLU -> xc (fp32 + tf32)
// ============================================================================
__global__ void conv_silu_kernel(const float* __restrict__ cw,
                                 const float* __restrict__ cb)
{
    int idx = blockIdx.x * blockDim.x + threadIdx.x;
    if (idx >= TOK * ED) return;
    int e = idx & (ED - 1);
    int t = idx >> 11;
    int l = t & (LL - 1);

    float w0 = cw[e * 4 + 0], w1 = cw[e * 4 + 1];
    float w2 = cw[e * 4 + 2], w3 = cw[e * 4 + 3];

    const float* col = g_xz + (size_t)t * (2 * ED) + e;
    float acc = cb[e] + w3 * col[0];
    if (l >= 1) acc = fmaf(w2, col[-(2 * ED)],     acc);
    if (l >= 2) acc = fmaf(w1, col[-2 * (2 * ED)], acc);
    if (l >= 3) acc = fmaf(w0, col[-3 * (2 * ED)], acc);

    float v = acc / (1.f + __expf(-acc));
    g_xc[idx]  = v;
    g_xct[idx] = f2tf32(v);
}

// ============================================================================
// Selective scan, 4-step batched + register double-buffer prefetch.
// 16-lane group per (b, ed) chain; lane = state index n.
// ============================================================================
__global__ void __launch_bounds__(256)
scan_kernel(const float* __restrict__ A_log, const float* __restrict__ Dvec)
{
    const int tid  = threadIdx.x;
    const int g    = blockIdx.x * 16 + (tid >> 4);
    const int lane = tid & 15;
    const int b    = g >> 11;
    const int ed   = g & (ED - 1);

    const float An = -__expf(A_log[ed * NS + lane]);
    const float Dv = Dvec[ed];

    const float* dptr  = g_delta + (size_t)(b * LL) * ED + ed;
    const float* xptr  = g_xc    + (size_t)(b * LL) * ED + ed;
    const float* zptr  = g_xz    + (size_t)(b * LL) * (2 * ED) + ED + ed;
    const float* bcptr = g_dbc   + (size_t)(b * LL) * DBCW + DTR + lane;
    uint32_t*    yptr  = g_yt    + (size_t)(b * LL) * ED + ed;

    float dv[2][4], xv[2][4], bv[2][4], cv[2][4], zv[2];

    auto load_batch = [&](int s, int l0) {
#pragma unroll
        for (int j = 0; j < 4; ++j) {
            dv[s][j] = dptr[(size_t)(l0 + j) * ED];
            xv[s][j] = xptr[(size_t)(l0 + j) * ED];
            bv[s][j] = bcptr[(size_t)(l0 + j) * DBCW];
            cv[s][j] = bcptr[(size_t)(l0 + j) * DBCW + NS];
        }
        zv[s] = zptr[(size_t)(l0 + (lane & 3)) * 2 * ED];
    };

    load_batch(0, 0);

    float h = 0.f;
    for (int l0 = 0; l0 < LL; l0 += 4) {
        const int s = (l0 >> 2) & 1;
        if (l0 + 4 < LL) load_batch(s ^ 1, l0 + 4);   // prefetch next batch

        float p0, p1, p2, p3;
        {
            float da;
            da = __expf(dv[s][0] * An); h = fmaf(da, h, dv[s][0] * bv[s][0] * xv[s][0]); p0 = h * cv[s][0];
            da = __expf(dv[s][1] * An); h = fmaf(da, h, dv[s][1] * bv[s][1] * xv[s][1]); p1 = h * cv[s][1];
            da = __expf(dv[s][2] * An); h = fmaf(da, h, dv[s][2] * bv[s][2] * xv[s][2]); p2 = h * cv[s][2];
            da = __expf(dv[s][3] * An); h = fmaf(da, h, dv[s][3] * bv[s][3] * xv[s][3]); p3 = h * cv[s][3];
        }
#pragma unroll
        for (int m = 1; m < 16; m <<= 1) {
            p0 += __shfl_xor_sync(0xffffffffu, p0, m);
            p1 += __shfl_xor_sync(0xffffffffu, p1, m);
            p2 += __shfl_xor_sync(0xffffffffu, p2, m);
            p3 += __shfl_xor_sync(0xffffffffu, p3, m);
        }
        if (lane < 4) {
            float p  = (lane == 0) ? p0 : (lane == 1) ? p1 : (lane == 2) ? p2 : p3;
            float xj = (lane == 0) ? xv[s][0] : (lane == 1) ? xv[s][1]
                     : (lane == 2) ? xv[s][2] : xv[s][3];
            float sg = zv[s] / (1.f + __expf(-zv[s]));
            yptr[(size_t)(l0 + lane) * ED] = f2tf32((p + Dv * xj) * sg);
        }
    }
}

// ============================================================================
extern "C" void kernel_launch(void* const* d_in, const int* in_sizes, int n_in,
                              void* d_out, int out_size)
{
    const float* x         = (const float*)d_in[0];
    const float* in_proj_w = (const float*)d_in[1];
    const float* conv_w    = (const float*)d_in[2];
    const float* conv_b    = (const float*)d_in[3];
    const float* x_proj_w  = (const float*)d_in[4];
    const float* dt_proj_w = (const float*)d_in[5];
    const float* dt_proj_b = (const float*)d_in[6];
    const float* A_log     = (const float*)d_in[7];
    const float* Dvec      = (const float*)d_in[8];
    const float* out_proj_w= (const float*)d_in[9];
    float* out = (float*)d_out;

    static float    *p_xz = nullptr, *p_delta = nullptr, *p_part = nullptr, *p_opart = nullptr;
    static uint32_t *p_xt, *p_win, *p_wxp, *p_wdt, *p_wout, *p_xct, *p_dbct, *p_yt;
    if (!p_xz) {
        cudaGetSymbolAddress((void**)&p_xz,    g_xz);
        cudaGetSymbolAddress((void**)&p_delta, g_delta);
        cudaGetSymbolAddress((void**)&p_part,  g_part);
        cudaGetSymbolAddress((void**)&p_opart, g_opart);
        cudaGetSymbolAddress((void**)&p_xt,    g_xt);
        cudaGetSymbolAddress((void**)&p_win,   g_wt_in);
        cudaGetSymbolAddress((void**)&p_wxp,   g_wt_xp);
        cudaGetSymbolAddress((void**)&p_wdt,   g_wt_dt);
        cudaGetSymbolAddress((void**)&p_wout,  g_wt_out);
        cudaGetSymbolAddress((void**)&p_xct,   g_xct);
        cudaGetSymbolAddress((void**)&p_dbct,  g_dbct);
        cudaGetSymbolAddress((void**)&p_yt,    g_yt);
        cudaFuncSetAttribute(gemm_tf32<0>, cudaFuncAttributeMaxDynamicSharedMemorySize, GEMM_SMEM);
        cudaFuncSetAttribute(gemm_tf32<1>, cudaFuncAttributeMaxDynamicSharedMemorySize, GEMM_SMEM);
        cudaFuncSetAttribute(gemm_tf32<3>, cudaFuncAttributeMaxDynamicSharedMemorySize, GEMM_SMEM);
    }

    // [0-2] tf32 conversions
    prep_w1<<<2048, 256>>>(in_proj_w);
    prep_w2<<<1024, 256>>>(dt_proj_w, out_proj_w, x_proj_w);
    prep_x <<<1024, 256>>>(x);

    // [3] xz = x @ in_proj_w : (2048x1024)@(1024x4096)   <- profiled launch
    gemm_tf32<0><<<dim3(2 * ED / 128, TOK / 128), 128, GEMM_SMEM>>>(
        p_xt, p_win, p_xz, TOK, 2 * ED, DM, DM, 2 * ED, 2 * ED, nullptr);

    // [4] depthwise causal conv + silu
    conv_silu_kernel<<<(TOK * ED + 255) / 256, 256>>>(conv_w, conv_b);

    // [5] xproj split-K: (2048x2048)@(2048x128), 8 K-chunks
    gemm_tf32<3><<<dim3(1, TOK / 128, KSPL), 128, GEMM_SMEM>>>(
        p_xct, p_wxp, p_part, TOK, DBCW, KCH, ED, DBCW, DBCW, nullptr);

    // [6] reduce partials -> dbc fp32 + tf32
    reduce_dbc<<<(TOK * DBCW / 4 + 255) / 256, 256>>>();

    // [7] delta = softplus(dbc[:, :64] @ dt_proj_w + b)
    gemm_tf32<1><<<dim3(ED / 128, TOK / 128), 128, GEMM_SMEM>>>(
        p_dbct, p_wdt, p_delta, TOK, ED, DTR, DBCW, ED, ED, dt_proj_b);

    // [8] selective scan -> y (tf32)
    scan_kernel<<<(BB * ED) / 16, 256>>>(A_log, Dvec);

    // [9] out_proj split-K x2: (2048x2048)@(2048x1024)
    gemm_tf32<3><<<dim3(DM / 128, TOK / 128, OSPL), 128, GEMM_SMEM>>>(
        p_yt, p_wout, p_opart, TOK, DM, ED / OSPL, ED, DM, DM, nullptr);

    // [10] reduce out partials -> d_out
    reduce_out<<<(TOK * DM / 4 + 255) / 256, 256>>>(out);
}

// round 8
// speedup vs baseline: 3.3714x; 1.2023x over previous
#include <cuda_runtime.h>
#include <cuda_fp16.h>
#include <math.h>
#include <stdint.h>

// Problem constants
#define BB    2
#define LL    1024
#define DM    1024
#define ED    2048
#define NS    16
#define DTR   64
#define TOK   (BB*LL)          // 2048
#define DBCW  128              // padded dbc width (64 dt + 16 B + 16 C + pad)
#define KSPL  8
#define KCH   (ED / KSPL)      // 256
#define OSPL  2                // split-K for out_proj

// -------- fp32 scratch --------
__device__ float    g_xz[(size_t)TOK * 2 * ED];
__device__ float    g_xc[(size_t)TOK * ED];
__device__ float    g_dbc[(size_t)TOK * DBCW];
__device__ float    g_delta[(size_t)TOK * ED];
__device__ float    g_part[(size_t)KSPL * TOK * DBCW];
__device__ float    g_opart[(size_t)OSPL * TOK * DM];
// -------- fp16 A-side operands (natural [M][K] layout) --------
__device__ __half   g_xh  [(size_t)TOK * DM];
__device__ __half   g_xch [(size_t)TOK * ED];
__device__ __half   g_dbch[(size_t)TOK * DBCW];
__device__ __half   g_yh  [(size_t)TOK * ED];
// -------- fp16 B-side weights, k-pair interleaved: u32[(K/2)][N] --------
__device__ uint32_t g_wh_in [(size_t)(DM/2)  * (2*ED)];
__device__ uint32_t g_wh_xp [(size_t)(ED/2)  * DBCW];
__device__ uint32_t g_wh_dt [(size_t)(DTR/2) * ED];
__device__ uint32_t g_wh_out[(size_t)(ED/2)  * DM];

__device__ __forceinline__ uint32_t pack2h(float a, float b) {
    __half2 h = __floats2half2_rn(a, b);
    return *(uint32_t*)&h;
}

// ============================================================================
// prep kernels: B weights -> k-pair interleaved fp16; x -> fp16
// ============================================================================
__global__ void prep_w1(const float* __restrict__ w_in)   // [DM][2ED]
{
    for (int i = blockIdx.x * blockDim.x + threadIdx.x; i < (DM/2) * 2 * ED;
         i += gridDim.x * blockDim.x) {
        int kp = i >> 12, n = i & 4095;
        g_wh_in[i] = pack2h(w_in[(size_t)(2*kp) * 4096 + n],
                            w_in[(size_t)(2*kp+1) * 4096 + n]);
    }
}

#define Q2A ((DTR/2) * ED)      // 65536
#define Q2B ((ED/2) * DM)       // 1048576
#define Q2C ((ED/2) * DBCW)     // 131072
__global__ void prep_w2(const float* __restrict__ w_dt,   // [DTR][ED]
                        const float* __restrict__ w_out,  // [ED][DM]
                        const float* __restrict__ w_xp)   // [ED][96]
{
    for (int i = blockIdx.x * blockDim.x + threadIdx.x; i < Q2A + Q2B + Q2C;
         i += gridDim.x * blockDim.x) {
        int j = i;
        if (j < Q2A) {
            int kp = j >> 11, n = j & 2047;
            g_wh_dt[j] = pack2h(w_dt[(size_t)(2*kp) * ED + n],
                                w_dt[(size_t)(2*kp+1) * ED + n]);
            continue;
        }
        j -= Q2A;
        if (j < Q2B) {
            int kp = j >> 10, n = j & 1023;
            g_wh_out[j] = pack2h(w_out[(size_t)(2*kp) * DM + n],
                                 w_out[(size_t)(2*kp+1) * DM + n]);
            continue;
        }
        j -= Q2B;
        {
            int kp = j >> 7, n = j & 127;
            float a = (n < 96) ? w_xp[(size_t)(2*kp) * 96 + n]   : 0.f;
            float b = (n < 96) ? w_xp[(size_t)(2*kp+1) * 96 + n] : 0.f;
            g_wh_xp[j] = pack2h(a, b);
        }
    }
}

__global__ void prep_x(const float* __restrict__ x)
{
    uint32_t* out = (uint32_t*)g_xh;
    const float2* in = (const float2*)x;
    for (int i = blockIdx.x * blockDim.x + threadIdx.x; i < TOK * DM / 2;
         i += gridDim.x * blockDim.x) {
        float2 v = in[i];
        out[i] = pack2h(v.x, v.y);
    }
}

// ============================================================================
// FP16 GEMM (m16n8k16, fp32 accum): 128x128 CTA tile, 128 thr / 4 warps,
// warp tile 64x64. All K-addressing in u32 units (1 u32 = 2 halves).
// Ku = K/2 (u32), lda = A row stride in u32, ldb = N (u32 per k-pair row).
// BK = 16 u32 = 32 halves per k-tile; 4-stage cp.async.
// EPI: 0 = fp32 C; 1 = +bias + softplus; 3 = split-K partial (blockIdx.z).
// ============================================================================
#define STG  4
#define APAD 20
#define BPAD 136
#define ASMSZ (128 * APAD)
#define BSMSZ (16 * BPAD)
#define GEMM_SMEM (STG * (ASMSZ + BSMSZ) * 4)

__device__ __forceinline__ void cpa16z(uint32_t dst, const void* src, bool valid) {
    int sz = valid ? 16 : 0;
    asm volatile("cp.async.cg.shared.global [%0], [%1], 16, %2;\n"
                 :: "r"(dst), "l"(src), "r"(sz));
}
__device__ __forceinline__ void cpa_commit() {
    asm volatile("cp.async.commit_group;\n");
}
template<int N>
__device__ __forceinline__ void cpa_wait() {
    asm volatile("cp.async.wait_group %0;\n" :: "n"(N));
}

template<int EPI>
__global__ void __launch_bounds__(128)
gemm_f16(const uint32_t* __restrict__ A, const uint32_t* __restrict__ B,
         float* __restrict__ C, int M, int N, int Ku,
         int lda, int ldb, int ldc, const float* __restrict__ bias)
{
    extern __shared__ __align__(16) uint32_t smem_u[];
    uint32_t* As = smem_u;
    uint32_t* Bs = smem_u + STG * ASMSZ;

    if (EPI == 3) {
        A += (size_t)blockIdx.z * Ku;          // Ku = chunk length (u32)
        B += (size_t)blockIdx.z * Ku * ldb;
        C += (size_t)blockIdx.z * M * ldc;
    }

    const int tid  = threadIdx.x;
    const int lane = tid & 31;
    const int wid  = tid >> 5;
    const int lm   = lane >> 2;    // 0..7
    const int lk   = lane & 3;     // 0..3

    const int bm = blockIdx.y * 128;
    const int bn = blockIdx.x * 128;
    const int wm = (wid >> 1) * 64;
    const int wn = (wid & 1) * 64;

    uint32_t oA[4], oB[4];
    const uint32_t *Ag[4], *Bg[4];
#pragma unroll
    for (int t = 0; t < 4; ++t) {
        int ia = tid + 128 * t;            // 0..511
        int ar = ia >> 2, ak = (ia & 3) << 2;
        oA[t] = (uint32_t)(ar * APAD + ak) * 4;
        Ag[t] = A + (size_t)(bm + ar) * lda + ak;
        int br = ia >> 5, bc = (ia & 31) << 2;
        oB[t] = (uint32_t)(br * BPAD + bc) * 4;
        Bg[t] = B + (size_t)br * ldb + bn + bc;
    }
    const uint32_t sAb = (uint32_t)__cvta_generic_to_shared(As);
    const uint32_t sBb = (uint32_t)__cvta_generic_to_shared(Bs);

    const int KT = Ku / 16;

    float acc[4][8][4];
#pragma unroll
    for (int i = 0; i < 4; ++i)
#pragma unroll
        for (int j = 0; j < 8; ++j)
#pragma unroll
            for (int r = 0; r < 4; ++r) acc[i][j][r] = 0.f;

    auto issue = [&](int kt) {
        bool v = kt < KT;
        int st = kt & (STG - 1);
        int ko = kt * 16;
        uint32_t ab = sAb + st * (ASMSZ * 4);
        uint32_t bb = sBb + st * (BSMSZ * 4);
#pragma unroll
        for (int t = 0; t < 4; ++t) cpa16z(ab + oA[t], Ag[t] + ko, v);
#pragma unroll
        for (int t = 0; t < 4; ++t) cpa16z(bb + oB[t], Bg[t] + (size_t)ko * ldb, v);
        cpa_commit();
    };

    issue(0); issue(1); issue(2);

    for (int kt = 0; kt < KT; ++kt) {
        cpa_wait<STG - 2>();
        __syncthreads();
        issue(kt + STG - 1);

        const uint32_t* Asb = As + (kt & (STG - 1)) * ASMSZ;
        const uint32_t* Bsb = Bs + (kt & (STG - 1)) * BSMSZ;
#pragma unroll
        for (int kb = 0; kb < 16; kb += 8) {   // kb indexes k-pair rows; each iter = k16
            uint32_t af[4][4], bf[8][2];
#pragma unroll
            for (int mt = 0; mt < 4; ++mt) {
                int m = wm + mt * 16 + lm;
                af[mt][0] = Asb[m * APAD + kb + lk];          // (m,   k=2lk..2lk+1)
                af[mt][1] = Asb[(m + 8) * APAD + kb + lk];    // (m+8, k=2lk..2lk+1)
                af[mt][2] = Asb[m * APAD + kb + 4 + lk];      // (m,   k=2lk+8..9)
                af[mt][3] = Asb[(m + 8) * APAD + kb + 4 + lk];
            }
#pragma unroll
            for (int nt = 0; nt < 8; ++nt) {
                int n = wn + nt * 8 + lm;
                bf[nt][0] = Bsb[(kb + lk) * BPAD + n];        // (k=2lk..2lk+1, n)
                bf[nt][1] = Bsb[(kb + 4 + lk) * BPAD + n];    // (k=2lk+8..9,  n)
            }
#pragma unroll
            for (int mt = 0; mt < 4; ++mt)
#pragma unroll
                for (int nt = 0; nt < 8; ++nt) {
                    asm volatile(
                        "mma.sync.aligned.m16n8k16.row.col.f32.f16.f16.f32 "
                        "{%0,%1,%2,%3}, {%4,%5,%6,%7}, {%8,%9}, {%0,%1,%2,%3};\n"
                        : "+f"(acc[mt][nt][0]), "+f"(acc[mt][nt][1]),
                          "+f"(acc[mt][nt][2]), "+f"(acc[mt][nt][3])
                        : "r"(af[mt][0]), "r"(af[mt][1]), "r"(af[mt][2]), "r"(af[mt][3]),
                          "r"(bf[nt][0]), "r"(bf[nt][1]));
                }
        }
    }

    // epilogue
#pragma unroll
    for (int mt = 0; mt < 4; ++mt) {
#pragma unroll
        for (int nt = 0; nt < 8; ++nt) {
            int row = bm + wm + mt * 16 + lm;
            int col = bn + wn + nt * 8 + lk * 2;
            float v0 = acc[mt][nt][0], v1 = acc[mt][nt][1];
            float v2 = acc[mt][nt][2], v3 = acc[mt][nt][3];
            if (EPI == 1) {
                float bb0 = bias[col], bb1 = bias[col + 1];
                v0 += bb0; v1 += bb1; v2 += bb0; v3 += bb1;
                v0 = (v0 > 20.f) ? v0 : log1pf(expf(v0));
                v1 = (v1 > 20.f) ? v1 : log1pf(expf(v1));
                v2 = (v2 > 20.f) ? v2 : log1pf(expf(v2));
                v3 = (v3 > 20.f) ? v3 : log1pf(expf(v3));
            }
            *(float2*)(C + (size_t)row * ldc + col)       = make_float2(v0, v1);
            *(float2*)(C + (size_t)(row + 8) * ldc + col) = make_float2(v2, v3);
        }
    }
}

// ============================================================================
// split-K reduces
// ============================================================================
__global__ void reduce_dbc()
{
    int i = blockIdx.x * blockDim.x + threadIdx.x;
    if (i >= TOK * DBCW / 4) return;
    const float4* p = (const float4*)g_part;
    float4 s = p[i];
#pragma unroll
    for (int k = 1; k < KSPL; ++k) {
        float4 t = p[(size_t)k * (TOK * DBCW / 4) + i];
        s.x += t.x; s.y += t.y; s.z += t.z; s.w += t.w;
    }
    ((float4*)g_dbc)[i] = s;
    ((uint2*)g_dbch)[i] = make_uint2(pack2h(s.x, s.y), pack2h(s.z, s.w));
}

__global__ void reduce_out(float* __restrict__ out)
{
    int i = blockIdx.x * blockDim.x + threadIdx.x;
    if (i >= TOK * DM / 4) return;
    const float4* p = (const float4*)g_opart;
    float4 a = p[i];
    float4 b = p[(size_t)(TOK * DM / 4) + i];
    ((float4*)out)[i] = make_float4(a.x + b.x, a.y + b.y, a.z + b.z, a.w + b.w);
}

// ============================================================================
// Depthwise causal conv1d (k=4) + bias + SiLU -> xc (fp32 + fp16)
// ============================================================================
__global__ void conv_silu_kernel(const float* __restrict__ cw,
                                 const float* __restrict__ cb)
{
    int idx = blockIdx.x * blockDim.x + threadIdx.x;
    if (idx >= TOK * ED) return;
    int e = idx & (ED - 1);
    int t = idx >> 11;
    int l = t & (LL - 1);

    float w0 = cw[e * 4 + 0], w1 = cw[e * 4 + 1];
    float w2 = cw[e * 4 + 2], w3 = cw[e * 4 + 3];

    const float* col = g_xz + (size_t)t * (2 * ED) + e;
    float acc = cb[e] + w3 * col[0];
    if (l >= 1) acc = fmaf(w2, col[-(2 * ED)],     acc);
    if (l >= 2) acc = fmaf(w1, col[-2 * (2 * ED)], acc);
    if (l >= 3) acc = fmaf(w0, col[-3 * (2 * ED)], acc);

    float v = acc / (1.f + __expf(-acc));
    g_xc[idx]  = v;
    g_xch[idx] = __float2half_rn(v);
}

// ============================================================================
// Selective scan, 4-step batched + register double-buffer prefetch.
// ============================================================================
__global__ void __launch_bounds__(256)
scan_kernel(const float* __restrict__ A_log, const float* __restrict__ Dvec)
{
    const int tid  = threadIdx.x;
    const int g    = blockIdx.x * 16 + (tid >> 4);
    const int lane = tid & 15;
    const int b    = g >> 11;
    const int ed   = g & (ED - 1);

    const float An = -__expf(A_log[ed * NS + lane]);
    const float Dv = Dvec[ed];

    const float* dptr  = g_delta + (size_t)(b * LL) * ED + ed;
    const float* xptr  = g_xc    + (size_t)(b * LL) * ED + ed;
    const float* zptr  = g_xz    + (size_t)(b * LL) * (2 * ED) + ED + ed;
    const float* bcptr = g_dbc   + (size_t)(b * LL) * DBCW + DTR + lane;
    __half*      yptr  = g_yh    + (size_t)(b * LL) * ED + ed;

    float dv[2][4], xv[2][4], bv[2][4], cv[2][4], zv[2];

    auto load_batch = [&](int s, int l0) {
#pragma unroll
        for (int j = 0; j < 4; ++j) {
            dv[s][j] = dptr[(size_t)(l0 + j) * ED];
            xv[s][j] = xptr[(size_t)(l0 + j) * ED];
            bv[s][j] = bcptr[(size_t)(l0 + j) * DBCW];
            cv[s][j] = bcptr[(size_t)(l0 + j) * DBCW + NS];
        }
        zv[s] = zptr[(size_t)(l0 + (lane & 3)) * 2 * ED];
    };

    load_batch(0, 0);

    float h = 0.f;
    for (int l0 = 0; l0 < LL; l0 += 4) {
        const int s = (l0 >> 2) & 1;
        if (l0 + 4 < LL) load_batch(s ^ 1, l0 + 4);   // prefetch next batch

        float p0, p1, p2, p3;
        {
            float da;
            da = __expf(dv[s][0] * An); h = fmaf(da, h, dv[s][0] * bv[s][0] * xv[s][0]); p0 = h * cv[s][0];
            da = __expf(dv[s][1] * An); h = fmaf(da, h, dv[s][1] * bv[s][1] * xv[s][1]); p1 = h * cv[s][1];
            da = __expf(dv[s][2] * An); h = fmaf(da, h, dv[s][2] * bv[s][2] * xv[s][2]); p2 = h * cv[s][2];
            da = __expf(dv[s][3] * An); h = fmaf(da, h, dv[s][3] * bv[s][3] * xv[s][3]); p3 = h * cv[s][3];
        }
#pragma unroll
        for (int m = 1; m < 16; m <<= 1) {
            p0 += __shfl_xor_sync(0xffffffffu, p0, m);
            p1 += __shfl_xor_sync(0xffffffffu, p1, m);
            p2 += __shfl_xor_sync(0xffffffffu, p2, m);
            p3 += __shfl_xor_sync(0xffffffffu, p3, m);
        }
        if (lane < 4) {
            float p  = (lane == 0) ? p0 : (lane == 1) ? p1 : (lane == 2) ? p2 : p3;
            float xj = (lane == 0) ? xv[s][0] : (lane == 1) ? xv[s][1]
                     : (lane == 2) ? xv[s][2] : xv[s][3];
            float sg = zv[s] / (1.f + __expf(-zv[s]));
            yptr[(size_t)(l0 + lane) * ED] = __float2half_rn((p + Dv * xj) * sg);
        }
    }
}

// ============================================================================
extern "C" void kernel_launch(void* const* d_in, const int* in_sizes, int n_in,
                              void* d_out, int out_size)
{
    const float* x         = (const float*)d_in[0];
    const float* in_proj_w = (const float*)d_in[1];
    const float* conv_w    = (const float*)d_in[2];
    const float* conv_b    = (const float*)d_in[3];
    const float* x_proj_w  = (const float*)d_in[4];
    const float* dt_proj_w = (const float*)d_in[5];
    const float* dt_proj_b = (const float*)d_in[6];
    const float* A_log     = (const float*)d_in[7];
    const float* Dvec      = (const float*)d_in[8];
    const float* out_proj_w= (const float*)d_in[9];
    float* out = (float*)d_out;

    static float    *p_xz = nullptr, *p_delta = nullptr, *p_part = nullptr, *p_opart = nullptr;
    static uint32_t *p_xh, *p_win, *p_wxp, *p_wdt, *p_wout, *p_xch, *p_dbch, *p_yh;
    if (!p_xz) {
        cudaGetSymbolAddress((void**)&p_xz,    g_xz);
        cudaGetSymbolAddress((void**)&p_delta, g_delta);
        cudaGetSymbolAddress((void**)&p_part,  g_part);
        cudaGetSymbolAddress((void**)&p_opart, g_opart);
        cudaGetSymbolAddress((void**)&p_xh,    g_xh);
        cudaGetSymbolAddress((void**)&p_win,   g_wh_in);
        cudaGetSymbolAddress((void**)&p_wxp,   g_wh_xp);
        cudaGetSymbolAddress((void**)&p_wdt,   g_wh_dt);
        cudaGetSymbolAddress((void**)&p_wout,  g_wh_out);
        cudaGetSymbolAddress((void**)&p_xch,   g_xch);
        cudaGetSymbolAddress((void**)&p_dbch,  g_dbch);
        cudaGetSymbolAddress((void**)&p_yh,    g_yh);
        cudaFuncSetAttribute(gemm_f16<0>, cudaFuncAttributeMaxDynamicSharedMemorySize, GEMM_SMEM);
        cudaFuncSetAttribute(gemm_f16<1>, cudaFuncAttributeMaxDynamicSharedMemorySize, GEMM_SMEM);
        cudaFuncSetAttribute(gemm_f16<3>, cudaFuncAttributeMaxDynamicSharedMemorySize, GEMM_SMEM);
    }

    // [0-2] fp16 conversions (B weights k-pair interleaved)
    prep_w1<<<2048, 256>>>(in_proj_w);
    prep_w2<<<1024, 256>>>(dt_proj_w, out_proj_w, x_proj_w);
    prep_x <<<1024, 256>>>(x);

    // [3] xz = x @ in_proj_w : Ku=512, lda=512(u32), ldb=4096
    gemm_f16<0><<<dim3(2 * ED / 128, TOK / 128), 128, GEMM_SMEM>>>(
        p_xh, p_win, p_xz, TOK, 2 * ED, DM / 2, DM / 2, 2 * ED, 2 * ED, nullptr);

    // [4] depthwise causal conv + silu
    conv_silu_kernel<<<(TOK * ED + 255) / 256, 256>>>(conv_w, conv_b);

    // [5] xproj split-K: chunk Ku=128, lda=1024, ldb=128
    gemm_f16<3><<<dim3(1, TOK / 128, KSPL), 128, GEMM_SMEM>>>(
        p_xch, p_wxp, p_part, TOK, DBCW, KCH / 2, ED / 2, DBCW, DBCW, nullptr);

    // [6] reduce partials -> dbc fp32 + fp16
    reduce_dbc<<<(TOK * DBCW / 4 + 255) / 256, 256>>>();

    // [7] delta = softplus(dbc[:, :64] @ dt_proj_w + b) : Ku=32, lda=64, ldb=2048
    gemm_f16<1><<<dim3(ED / 128, TOK / 128), 128, GEMM_SMEM>>>(
        p_dbch, p_wdt, p_delta, TOK, ED, DTR / 2, DBCW / 2, ED, ED, dt_proj_b);

    // [8] selective scan -> y (fp16)
    scan_kernel<<<(BB * ED) / 16, 256>>>(A_log, Dvec);

    // [9] out_proj split-K x2: chunk Ku=512, lda=1024, ldb=1024
    gemm_f16<3><<<dim3(DM / 128, TOK / 128, OSPL), 128, GEMM_SMEM>>>(
        p_yh, p_wout, p_opart, TOK, DM, ED / (2 * OSPL), ED / 2, DM, DM, nullptr);

    // [10] reduce out partials -> d_out
    reduce_out<<<(TOK * DM / 4 + 255) / 256, 256>>>(out);
}

// round 9
// speedup vs baseline: 4.1456x; 1.2296x over previous
#include <cuda_runtime.h>
#include <cuda_fp16.h>
#include <math.h>
#include <stdint.h>

// Problem constants
#define BB    2
#define LL    1024
#define DM    1024
#define ED    2048
#define NS    16
#define DTR   64
#define TOK   (BB*LL)          // 2048
#define DBCW  128              // padded dbc width (64 dt + 16 B + 16 C + pad)
#define KSPL  8
#define KCH   (ED / KSPL)      // 256
#define OSPL  2                // split-K for out_proj
#define SEG   8                // scan segments
#define SEGL  (LL / SEG)       // 128

// -------- fp32 scratch --------
__device__ float    g_xz[(size_t)TOK * 2 * ED];
__device__ float    g_xc[(size_t)TOK * ED];
__device__ float    g_dbc[(size_t)TOK * DBCW];
__device__ float    g_delta[(size_t)TOK * ED];
__device__ float    g_part[(size_t)KSPL * TOK * DBCW];
__device__ float    g_opart[(size_t)OSPL * TOK * DM];
// scan segment state: index ((b*SEG+seg)*ED+ed)*NS+lane
__device__ float    g_segP[(size_t)BB * SEG * ED * NS];
__device__ float    g_segq[(size_t)BB * SEG * ED * NS];
__device__ float    g_hst [(size_t)BB * SEG * ED * NS];
// -------- fp16 A-side operands --------
__device__ __half   g_xh  [(size_t)TOK * DM];
__device__ __half   g_xch [(size_t)TOK * ED];
__device__ __half   g_dbch[(size_t)TOK * DBCW];
__device__ __half   g_yh  [(size_t)TOK * ED];
// -------- fp16 B-side weights, k-pair interleaved: u32[(K/2)][N] --------
__device__ uint32_t g_wh_in [(size_t)(DM/2)  * (2*ED)];
__device__ uint32_t g_wh_xp [(size_t)(ED/2)  * DBCW];
__device__ uint32_t g_wh_dt [(size_t)(DTR/2) * ED];
__device__ uint32_t g_wh_out[(size_t)(ED/2)  * DM];

__device__ __forceinline__ uint32_t pack2h(float a, float b) {
    __half2 h = __floats2half2_rn(a, b);
    return *(uint32_t*)&h;
}

// ============================================================================
// prep kernels (2 launches so launch index 3 = conv for profiling)
// ============================================================================
#define W1SZ ((DM/2) * 2 * ED)   // 2097152
#define Q2A ((DTR/2) * ED)       // 65536
#define Q2B ((ED/2) * DM)        // 1048576
#define Q2C ((ED/2) * DBCW)      // 131072
__global__ void prep_weights(const float* __restrict__ w_in,
                             const float* __restrict__ w_dt,
                             const float* __restrict__ w_out,
                             const float* __restrict__ w_xp)
{
    for (int i = blockIdx.x * blockDim.x + threadIdx.x;
         i < W1SZ + Q2A + Q2B + Q2C; i += gridDim.x * blockDim.x) {
        int j = i;
        if (j < W1SZ) {
            int kp = j >> 12, n = j & 4095;
            g_wh_in[j] = pack2h(w_in[(size_t)(2*kp) * 4096 + n],
                                w_in[(size_t)(2*kp+1) * 4096 + n]);
            continue;
        }
        j -= W1SZ;
        if (j < Q2A) {
            int kp = j >> 11, n = j & 2047;
            g_wh_dt[j] = pack2h(w_dt[(size_t)(2*kp) * ED + n],
                                w_dt[(size_t)(2*kp+1) * ED + n]);
            continue;
        }
        j -= Q2A;
        if (j < Q2B) {
            int kp = j >> 10, n = j & 1023;
            g_wh_out[j] = pack2h(w_out[(size_t)(2*kp) * DM + n],
                                 w_out[(size_t)(2*kp+1) * DM + n]);
            continue;
        }
        j -= Q2B;
        {
            int kp = j >> 7, n = j & 127;
            float a = (n < 96) ? w_xp[(size_t)(2*kp) * 96 + n]   : 0.f;
            float b = (n < 96) ? w_xp[(size_t)(2*kp+1) * 96 + n] : 0.f;
            g_wh_xp[j] = pack2h(a, b);
        }
    }
}

__global__ void prep_x(const float* __restrict__ x)
{
    uint32_t* out = (uint32_t*)g_xh;
    const float2* in = (const float2*)x;
    for (int i = blockIdx.x * blockDim.x + threadIdx.x; i < TOK * DM / 2;
         i += gridDim.x * blockDim.x) {
        float2 v = in[i];
        out[i] = pack2h(v.x, v.y);
    }
}

// ============================================================================
// FP16 GEMM (m16n8k16, fp32 accum): 128x128 CTA tile, 128 thr / 4 warps,
// warp tile 64x64, K-addressing in u32 units, 4-stage cp.async.
// EPI: 0 = fp32 C; 1 = +bias + softplus; 3 = split-K partial (blockIdx.z).
// ============================================================================
#define STG  4
#define APAD 20
#define BPAD 136
#define ASMSZ (128 * APAD)
#define BSMSZ (16 * BPAD)
#define GEMM_SMEM (STG * (ASMSZ + BSMSZ) * 4)

__device__ __forceinline__ void cpa16z(uint32_t dst, const void* src, bool valid) {
    int sz = valid ? 16 : 0;
    asm volatile("cp.async.cg.shared.global [%0], [%1], 16, %2;\n"
                 :: "r"(dst), "l"(src), "r"(sz));
}
__device__ __forceinline__ void cpa_commit() {
    asm volatile("cp.async.commit_group;\n");
}
template<int N>
__device__ __forceinline__ void cpa_wait() {
    asm volatile("cp.async.wait_group %0;\n" :: "n"(N));
}

template<int EPI>
__global__ void __launch_bounds__(128)
gemm_f16(const uint32_t* __restrict__ A, const uint32_t* __restrict__ B,
         float* __restrict__ C, int M, int N, int Ku,
         int lda, int ldb, int ldc, const float* __restrict__ bias)
{
    extern __shared__ __align__(16) uint32_t smem_u[];
    uint32_t* As = smem_u;
    uint32_t* Bs = smem_u + STG * ASMSZ;

    if (EPI == 3) {
        A += (size_t)blockIdx.z * Ku;
        B += (size_t)blockIdx.z * Ku * ldb;
        C += (size_t)blockIdx.z * M * ldc;
    }

    const int tid  = threadIdx.x;
    const int lane = tid & 31;
    const int wid  = tid >> 5;
    const int lm   = lane >> 2;
    const int lk   = lane & 3;

    const int bm = blockIdx.y * 128;
    const int bn = blockIdx.x * 128;
    const int wm = (wid >> 1) * 64;
    const int wn = (wid & 1) * 64;

    uint32_t oA[4], oB[4];
    const uint32_t *Ag[4], *Bg[4];
#pragma unroll
    for (int t = 0; t < 4; ++t) {
        int ia = tid + 128 * t;
        int ar = ia >> 2, ak = (ia & 3) << 2;
        oA[t] = (uint32_t)(ar * APAD + ak) * 4;
        Ag[t] = A + (size_t)(bm + ar) * lda + ak;
        int br = ia >> 5, bc = (ia & 31) << 2;
        oB[t] = (uint32_t)(br * BPAD + bc) * 4;
        Bg[t] = B + (size_t)br * ldb + bn + bc;
    }
    const uint32_t sAb = (uint32_t)__cvta_generic_to_shared(As);
    const uint32_t sBb = (uint32_t)__cvta_generic_to_shared(Bs);

    const int KT = Ku / 16;

    float acc[4][8][4];
#pragma unroll
    for (int i = 0; i < 4; ++i)
#pragma unroll
        for (int j = 0; j < 8; ++j)
#pragma unroll
            for (int r = 0; r < 4; ++r) acc[i][j][r] = 0.f;

    auto issue = [&](int kt) {
        bool v = kt < KT;
        int st = kt & (STG - 1);
        int ko = kt * 16;
        uint32_t ab = sAb + st * (ASMSZ * 4);
        uint32_t bb = sBb + st * (BSMSZ * 4);
#pragma unroll
        for (int t = 0; t < 4; ++t) cpa16z(ab + oA[t], Ag[t] + ko, v);
#pragma unroll
        for (int t = 0; t < 4; ++t) cpa16z(bb + oB[t], Bg[t] + (size_t)ko * ldb, v);
        cpa_commit();
    };

    issue(0); issue(1); issue(2);

    for (int kt = 0; kt < KT; ++kt) {
        cpa_wait<STG - 2>();
        __syncthreads();
        issue(kt + STG - 1);

        const uint32_t* Asb = As + (kt & (STG - 1)) * ASMSZ;
        const uint32_t* Bsb = Bs + (kt & (STG - 1)) * BSMSZ;
#pragma unroll
        for (int kb = 0; kb < 16; kb += 8) {
            uint32_t af[4][4], bf[8][2];
#pragma unroll
            for (int mt = 0; mt < 4; ++mt) {
                int m = wm + mt * 16 + lm;
                af[mt][0] = Asb[m * APAD + kb + lk];
                af[mt][1] = Asb[(m + 8) * APAD + kb + lk];
                af[mt][2] = Asb[m * APAD + kb + 4 + lk];
                af[mt][3] = Asb[(m + 8) * APAD + kb + 4 + lk];
            }
#pragma unroll
            for (int nt = 0; nt < 8; ++nt) {
                int n = wn + nt * 8 + lm;
                bf[nt][0] = Bsb[(kb + lk) * BPAD + n];
                bf[nt][1] = Bsb[(kb + 4 + lk) * BPAD + n];
            }
#pragma unroll
            for (int mt = 0; mt < 4; ++mt)
#pragma unroll
                for (int nt = 0; nt < 8; ++nt) {
                    asm volatile(
                        "mma.sync.aligned.m16n8k16.row.col.f32.f16.f16.f32 "
                        "{%0,%1,%2,%3}, {%4,%5,%6,%7}, {%8,%9}, {%0,%1,%2,%3};\n"
                        : "+f"(acc[mt][nt][0]), "+f"(acc[mt][nt][1]),
                          "+f"(acc[mt][nt][2]), "+f"(acc[mt][nt][3])
                        : "r"(af[mt][0]), "r"(af[mt][1]), "r"(af[mt][2]), "r"(af[mt][3]),
                          "r"(bf[nt][0]), "r"(bf[nt][1]));
                }
        }
    }

#pragma unroll
    for (int mt = 0; mt < 4; ++mt) {
#pragma unroll
        for (int nt = 0; nt < 8; ++nt) {
            int row = bm + wm + mt * 16 + lm;
            int col = bn + wn + nt * 8 + lk * 2;
            float v0 = acc[mt][nt][0], v1 = acc[mt][nt][1];
            float v2 = acc[mt][nt][2], v3 = acc[mt][nt][3];
            if (EPI == 1) {
                float bb0 = bias[col], bb1 = bias[col + 1];
                v0 += bb0; v1 += bb1; v2 += bb0; v3 += bb1;
                v0 = (v0 > 20.f) ? v0 : log1pf(expf(v0));
                v1 = (v1 > 20.f) ? v1 : log1pf(expf(v1));
                v2 = (v2 > 20.f) ? v2 : log1pf(expf(v2));
                v3 = (v3 > 20.f) ? v3 : log1pf(expf(v3));
            }
            *(float2*)(C + (size_t)row * ldc + col)       = make_float2(v0, v1);
            *(float2*)(C + (size_t)(row + 8) * ldc + col) = make_float2(v2, v3);
        }
    }
}

// ============================================================================
// split-K reduces
// ============================================================================
__global__ void reduce_dbc()
{
    int i = blockIdx.x * blockDim.x + threadIdx.x;
    if (i >= TOK * DBCW / 4) return;
    const float4* p = (const float4*)g_part;
    float4 s = p[i];
#pragma unroll
    for (int k = 1; k < KSPL; ++k) {
        float4 t = p[(size_t)k * (TOK * DBCW / 4) + i];
        s.x += t.x; s.y += t.y; s.z += t.z; s.w += t.w;
    }
    ((float4*)g_dbc)[i] = s;
    ((uint2*)g_dbch)[i] = make_uint2(pack2h(s.x, s.y), pack2h(s.z, s.w));
}

__global__ void reduce_out(float* __restrict__ out)
{
    int i = blockIdx.x * blockDim.x + threadIdx.x;
    if (i >= TOK * DM / 4) return;
    const float4* p = (const float4*)g_opart;
    float4 a = p[i];
    float4 b = p[(size_t)(TOK * DM / 4) + i];
    ((float4*)out)[i] = make_float4(a.x + b.x, a.y + b.y, a.z + b.z, a.w + b.w);
}

// ============================================================================
// Depthwise causal conv1d (k=4) + bias + SiLU -> xc (fp32 + fp16)
// ============================================================================
__global__ void conv_silu_kernel(const float* __restrict__ cw,
                                 const float* __restrict__ cb)
{
    int idx = blockIdx.x * blockDim.x + threadIdx.x;
    if (idx >= TOK * ED) return;
    int e = idx & (ED - 1);
    int t = idx >> 11;
    int l = t & (LL - 1);

    float w0 = cw[e * 4 + 0], w1 = cw[e * 4 + 1];
    float w2 = cw[e * 4 + 2], w3 = cw[e * 4 + 3];

    const float* col = g_xz + (size_t)t * (2 * ED) + e;
    float acc = cb[e] + w3 * col[0];
    if (l >= 1) acc = fmaf(w2, col[-(2 * ED)],     acc);
    if (l >= 2) acc = fmaf(w1, col[-2 * (2 * ED)], acc);
    if (l >= 3) acc = fmaf(w0, col[-3 * (2 * ED)], acc);

    float v = acc / (1.f + __expf(-acc));
    g_xc[idx]  = v;
    g_xch[idx] = __float2half_rn(v);
}

// ============================================================================
// Segmented selective scan.
// Group index g = (b*SEG+seg)*ED + ed ; 16 lanes = state index n.
// P1: per-segment (P = exp(An*sum d), q = zero-state scan end).
// P2: combine over segments -> h_start.
// P3: recompute with h_start, full outputs.
// ============================================================================
__global__ void __launch_bounds__(256)
scan_p1(const float* __restrict__ A_log)
{
    const int tid  = threadIdx.x;
    const int g    = blockIdx.x * 16 + (tid >> 4);   // 0..32767
    const int lane = tid & 15;
    const int ed   = g & (ED - 1);
    const int sb   = g >> 11;            // b*SEG+seg, 0..15
    const int b    = sb >> 3;
    const int seg  = sb & (SEG - 1);

    const float An = -__expf(A_log[ed * NS + lane]);

    const size_t tok0 = (size_t)(b * LL + seg * SEGL);
    const float* dptr  = g_delta + tok0 * ED + ed;
    const float* xptr  = g_xc    + tok0 * ED + ed;
    const float* bcptr = g_dbc   + tok0 * DBCW + DTR + lane;

    float dv[2][4], xv[2][4], bv[2][4];
    auto load_batch = [&](int s, int l0) {
#pragma unroll
        for (int j = 0; j < 4; ++j) {
            dv[s][j] = dptr[(size_t)(l0 + j) * ED];
            xv[s][j] = xptr[(size_t)(l0 + j) * ED];
            bv[s][j] = bcptr[(size_t)(l0 + j) * DBCW];
        }
    };
    load_batch(0, 0);

    float h = 0.f, sumd = 0.f;
    for (int l0 = 0; l0 < SEGL; l0 += 4) {
        const int s = (l0 >> 2) & 1;
        if (l0 + 4 < SEGL) load_batch(s ^ 1, l0 + 4);
#pragma unroll
        for (int j = 0; j < 4; ++j) {
            sumd += dv[s][j];
            float da = __expf(dv[s][j] * An);
            h = fmaf(da, h, dv[s][j] * bv[s][j] * xv[s][j]);
        }
    }
    g_segq[(size_t)g * NS + lane] = h;
    g_segP[(size_t)g * NS + lane] = __expf(An * sumd);
}

__global__ void __launch_bounds__(256)
scan_p2()
{
    const int tid  = threadIdx.x;
    const int cg   = blockIdx.x * 16 + (tid >> 4);   // 0..4095
    const int lane = tid & 15;
    const int ed   = cg & (ED - 1);
    const int b    = cg >> 11;

    float hs = 0.f;
#pragma unroll
    for (int s = 0; s < SEG; ++s) {
        size_t idx = ((size_t)((b * SEG + s) * ED + ed)) * NS + lane;
        g_hst[idx] = hs;
        hs = fmaf(g_segP[idx], hs, g_segq[idx]);
    }
}

__global__ void __launch_bounds__(256)
scan_p3(const float* __restrict__ A_log, const float* __restrict__ Dvec)
{
    const int tid  = threadIdx.x;
    const int g    = blockIdx.x * 16 + (tid >> 4);   // 0..32767
    const int lane = tid & 15;
    const int ed   = g & (ED - 1);
    const int sb   = g >> 11;
    const int b    = sb >> 3;
    const int seg  = sb & (SEG - 1);

    const float An = -__expf(A_log[ed * NS + lane]);
    const float Dv = Dvec[ed];

    const size_t tok0 = (size_t)(b * LL + seg * SEGL);
    const float* dptr  = g_delta + tok0 * ED + ed;
    const float* xptr  = g_xc    + tok0 * ED + ed;
    const float* zptr  = g_xz    + tok0 * (2 * ED) + ED + ed;
    const float* bcptr = g_dbc   + tok0 * DBCW + DTR + lane;
    __half*      yptr  = g_yh    + tok0 * ED + ed;

    float dv[2][4], xv[2][4], bv[2][4], cv[2][4], zv[2];
    auto load_batch = [&](int s, int l0) {
#pragma unroll
        for (int j = 0; j < 4; ++j) {
            dv[s][j] = dptr[(size_t)(l0 + j) * ED];
            xv[s][j] = xptr[(size_t)(l0 + j) * ED];
            bv[s][j] = bcptr[(size_t)(l0 + j) * DBCW];
            cv[s][j] = bcptr[(size_t)(l0 + j) * DBCW + NS];
        }
        zv[s] = zptr[(size_t)(l0 + (lane & 3)) * 2 * ED];
    };
    load_batch(0, 0);

    float h = g_hst[(size_t)g * NS + lane];

    for (int l0 = 0; l0 < SEGL; l0 += 4) {
        const int s = (l0 >> 2) & 1;
        if (l0 + 4 < SEGL) load_batch(s ^ 1, l0 + 4);

        float p0, p1, p2, p3;
        {
            float da;
            da = __expf(dv[s][0] * An); h = fmaf(da, h, dv[s][0] * bv[s][0] * xv[s][0]); p0 = h * cv[s][0];
            da = __expf(dv[s][1] * An); h = fmaf(da, h, dv[s][1] * bv[s][1] * xv[s][1]); p1 = h * cv[s][1];
            da = __expf(dv[s][2] * An); h = fmaf(da, h, dv[s][2] * bv[s][2] * xv[s][2]); p2 = h * cv[s][2];
            da = __expf(dv[s][3] * An); h = fmaf(da, h, dv[s][3] * bv[s][3] * xv[s][3]); p3 = h * cv[s][3];
        }
#pragma unroll
        for (int m = 1; m < 16; m <<= 1) {
            p0 += __shfl_xor_sync(0xffffffffu, p0, m);
            p1 += __shfl_xor_sync(0xffffffffu, p1, m);
            p2 += __shfl_xor_sync(0xffffffffu, p2, m);
            p3 += __shfl_xor_sync(0xffffffffu, p3, m);
        }
        if (lane < 4) {
            float p  = (lane == 0) ? p0 : (lane == 1) ? p1 : (lane == 2) ? p2 : p3;
            float xj = (lane == 0) ? xv[s][0] : (lane == 1) ? xv[s][1]
                     : (lane == 2) ? xv[s][2] : xv[s][3];
            float sg = zv[s] / (1.f + __expf(-zv[s]));
            yptr[(size_t)(l0 + lane) * ED] = __float2half_rn((p + Dv * xj) * sg);
        }
    }
}

// ============================================================================
extern "C" void kernel_launch(void* const* d_in, const int* in_sizes, int n_in,
                              void* d_out, int out_size)
{
    const float* x         = (const float*)d_in[0];
    const float* in_proj_w = (const float*)d_in[1];
    const float* conv_w    = (const float*)d_in[2];
    const float* conv_b    = (const float*)d_in[3];
    const float* x_proj_w  = (const float*)d_in[4];
    const float* dt_proj_w = (const float*)d_in[5];
    const float* dt_proj_b = (const float*)d_in[6];
    const float* A_log     = (const float*)d_in[7];
    const float* Dvec      = (const float*)d_in[8];
    const float* out_proj_w= (const float*)d_in[9];
    float* out = (float*)d_out;

    static float    *p_xz = nullptr, *p_delta = nullptr, *p_part = nullptr, *p_opart = nullptr;
    static uint32_t *p_xh, *p_win, *p_wxp, *p_wdt, *p_wout, *p_xch, *p_dbch, *p_yh;
    if (!p_xz) {
        cudaGetSymbolAddress((void**)&p_xz,    g_xz);
        cudaGetSymbolAddress((void**)&p_delta, g_delta);
        cudaGetSymbolAddress((void**)&p_part,  g_part);
        cudaGetSymbolAddress((void**)&p_opart, g_opart);
        cudaGetSymbolAddress((void**)&p_xh,    g_xh);
        cudaGetSymbolAddress((void**)&p_win,   g_wh_in);
        cudaGetSymbolAddress((void**)&p_wxp,   g_wh_xp);
        cudaGetSymbolAddress((void**)&p_wdt,   g_wh_dt);
        cudaGetSymbolAddress((void**)&p_wout,  g_wh_out);
        cudaGetSymbolAddress((void**)&p_xch,   g_xch);
        cudaGetSymbolAddress((void**)&p_dbch,  g_dbch);
        cudaGetSymbolAddress((void**)&p_yh,    g_yh);
        cudaFuncSetAttribute(gemm_f16<0>, cudaFuncAttributeMaxDynamicSharedMemorySize, GEMM_SMEM);
        cudaFuncSetAttribute(gemm_f16<1>, cudaFuncAttributeMaxDynamicSharedMemorySize, GEMM_SMEM);
        cudaFuncSetAttribute(gemm_f16<3>, cudaFuncAttributeMaxDynamicSharedMemorySize, GEMM_SMEM);
    }

    // [0-1] fp16 conversions
    prep_weights<<<2048, 256>>>(in_proj_w, dt_proj_w, out_proj_w, x_proj_w);
    prep_x<<<1024, 256>>>(x);

    // [2] xz = x @ in_proj_w
    gemm_f16<0><<<dim3(2 * ED / 128, TOK / 128), 128, GEMM_SMEM>>>(
        p_xh, p_win, p_xz, TOK, 2 * ED, DM / 2, DM / 2, 2 * ED, 2 * ED, nullptr);

    // [3] depthwise causal conv + silu      <- profiled launch
    conv_silu_kernel<<<(TOK * ED + 255) / 256, 256>>>(conv_w, conv_b);

    // [4] xproj split-K
    gemm_f16<3><<<dim3(1, TOK / 128, KSPL), 128, GEMM_SMEM>>>(
        p_xch, p_wxp, p_part, TOK, DBCW, KCH / 2, ED / 2, DBCW, DBCW, nullptr);

    // [5] reduce partials -> dbc fp32 + fp16
    reduce_dbc<<<(TOK * DBCW / 4 + 255) / 256, 256>>>();

    // [6] delta = softplus(dbc[:, :64] @ dt_proj_w + b)
    gemm_f16<1><<<dim3(ED / 128, TOK / 128), 128, GEMM_SMEM>>>(
        p_dbch, p_wdt, p_delta, TOK, ED, DTR / 2, DBCW / 2, ED, ED, dt_proj_b);

    // [7-9] segmented selective scan -> y (fp16)
    scan_p1<<<BB * SEG * ED / 16, 256>>>(A_log);
    scan_p2<<<BB * ED / 16, 256>>>();
    scan_p3<<<BB * SEG * ED / 16, 256>>>(A_log, Dvec);

    // [10] out_proj split-K x2
    gemm_f16<3><<<dim3(DM / 128, TOK / 128, OSPL), 128, GEMM_SMEM>>>(
        p_yh, p_wout, p_opart, TOK, DM, ED / (2 * OSPL), ED / 2, DM, DM, nullptr);

    // [11] reduce out partials -> d_out
    reduce_out<<<(TOK * DM / 4 + 255) / 256, 256>>>(out);
}

// round 10
// speedup vs baseline: 5.6022x; 1.3514x over previous
#include <cuda_runtime.h>
#include <cuda_fp16.h>
#include <math.h>
#include <stdint.h>

// Problem constants
#define BB    2
#define LL    1024
#define DM    1024
#define ED    2048
#define NS    16
#define DTR   64
#define TOK   (BB*LL)          // 2048
#define DBCW  128              // padded dbc width (64 dt + 16 B + 16 C + pad)
#define KSPL  8
#define KCH   (ED / KSPL)      // 256
#define OSPL  2                // split-K for out_proj
#define SEG   8                // scan segments
#define SEGL  (LL / SEG)       // 128

// -------- fp32 scratch --------
__device__ float    g_xz[(size_t)TOK * 2 * ED];
__device__ float    g_xc[(size_t)TOK * ED];
__device__ float    g_dbc[(size_t)TOK * DBCW];
__device__ float    g_delta[(size_t)TOK * ED];
__device__ float    g_part[(size_t)KSPL * TOK * DBCW];
__device__ float    g_opart[(size_t)OSPL * TOK * DM];
// scan segment state: index ((b*SEG+seg)*ED+ed)*NS+lane
__device__ float    g_segP[(size_t)BB * SEG * ED * NS];
__device__ float    g_segq[(size_t)BB * SEG * ED * NS];
__device__ float    g_hst [(size_t)BB * SEG * ED * NS];
// -------- fp16 A-side operands --------
__device__ __half   g_xh  [(size_t)TOK * DM];
__device__ __half   g_xch [(size_t)TOK * ED];
__device__ __half   g_dbch[(size_t)TOK * DBCW];
__device__ __half   g_yh  [(size_t)TOK * ED];
// -------- fp16 B-side weights, k-pair interleaved: u32[(K/2)][N] --------
__device__ uint32_t g_wh_in [(size_t)(DM/2)  * (2*ED)];
__device__ uint32_t g_wh_xp [(size_t)(ED/2)  * DBCW];
__device__ uint32_t g_wh_dt [(size_t)(DTR/2) * ED];
__device__ uint32_t g_wh_out[(size_t)(ED/2)  * DM];

__device__ __forceinline__ uint32_t pack2h(float a, float b) {
    __half2 h = __floats2half2_rn(a, b);
    return *(uint32_t*)&h;
}

// ============================================================================
// prep kernels
// ============================================================================
#define W1SZ ((DM/2) * 2 * ED)   // 2097152
#define Q2A ((DTR/2) * ED)       // 65536
#define Q2B ((ED/2) * DM)        // 1048576
#define Q2C ((ED/2) * DBCW)      // 131072
__global__ void prep_weights(const float* __restrict__ w_in,
                             const float* __restrict__ w_dt,
                             const float* __restrict__ w_out,
                             const float* __restrict__ w_xp)
{
    for (int i = blockIdx.x * blockDim.x + threadIdx.x;
         i < W1SZ + Q2A + Q2B + Q2C; i += gridDim.x * blockDim.x) {
        int j = i;
        if (j < W1SZ) {
            int kp = j >> 12, n = j & 4095;
            g_wh_in[j] = pack2h(w_in[(size_t)(2*kp) * 4096 + n],
                                w_in[(size_t)(2*kp+1) * 4096 + n]);
            continue;
        }
        j -= W1SZ;
        if (j < Q2A) {
            int kp = j >> 11, n = j & 2047;
            g_wh_dt[j] = pack2h(w_dt[(size_t)(2*kp) * ED + n],
                                w_dt[(size_t)(2*kp+1) * ED + n]);
            continue;
        }
        j -= Q2A;
        if (j < Q2B) {
            int kp = j >> 10, n = j & 1023;
            g_wh_out[j] = pack2h(w_out[(size_t)(2*kp) * DM + n],
                                 w_out[(size_t)(2*kp+1) * DM + n]);
            continue;
        }
        j -= Q2B;
        {
            int kp = j >> 7, n = j & 127;
            float a = (n < 96) ? w_xp[(size_t)(2*kp) * 96 + n]   : 0.f;
            float b = (n < 96) ? w_xp[(size_t)(2*kp+1) * 96 + n] : 0.f;
            g_wh_xp[j] = pack2h(a, b);
        }
    }
}

__global__ void prep_x(const float* __restrict__ x)
{
    uint32_t* out = (uint32_t*)g_xh;
    const float2* in = (const float2*)x;
    for (int i = blockIdx.x * blockDim.x + threadIdx.x; i < TOK * DM / 2;
         i += gridDim.x * blockDim.x) {
        float2 v = in[i];
        out[i] = pack2h(v.x, v.y);
    }
}

// ============================================================================
// FP16 GEMM (m16n8k16, fp32 accum): 128x128 CTA tile, 128 thr / 4 warps,
// warp tile 64x64, K-addressing in u32 units, 4-stage cp.async.
// EPI: 0 = fp32 C; 1 = +bias + softplus; 3 = split-K partial (blockIdx.z).
// ============================================================================
#define STG  4
#define APAD 20
#define BPAD 136
#define ASMSZ (128 * APAD)
#define BSMSZ (16 * BPAD)
#define GEMM_SMEM (STG * (ASMSZ + BSMSZ) * 4)

__device__ __forceinline__ void cpa16z(uint32_t dst, const void* src, bool valid) {
    int sz = valid ? 16 : 0;
    asm volatile("cp.async.cg.shared.global [%0], [%1], 16, %2;\n"
                 :: "r"(dst), "l"(src), "r"(sz));
}
__device__ __forceinline__ void cpa_commit() {
    asm volatile("cp.async.commit_group;\n");
}
template<int N>
__device__ __forceinline__ void cpa_wait() {
    asm volatile("cp.async.wait_group %0;\n" :: "n"(N));
}

template<int EPI>
__global__ void __launch_bounds__(128)
gemm_f16(const uint32_t* __restrict__ A, const uint32_t* __restrict__ B,
         float* __restrict__ C, int M, int N, int Ku,
         int lda, int ldb, int ldc, const float* __restrict__ bias)
{
    extern __shared__ __align__(16) uint32_t smem_u[];
    uint32_t* As = smem_u;
    uint32_t* Bs = smem_u + STG * ASMSZ;

    if (EPI == 3) {
        A += (size_t)blockIdx.z * Ku;
        B += (size_t)blockIdx.z * Ku * ldb;
        C += (size_t)blockIdx.z * M * ldc;
    }

    const int tid  = threadIdx.x;
    const int lane = tid & 31;
    const int wid  = tid >> 5;
    const int lm   = lane >> 2;
    const int lk   = lane & 3;

    const int bm = blockIdx.y * 128;
    const int bn = blockIdx.x * 128;
    const int wm = (wid >> 1) * 64;
    const int wn = (wid & 1) * 64;

    uint32_t oA[4], oB[4];
    const uint32_t *Ag[4], *Bg[4];
#pragma unroll
    for (int t = 0; t < 4; ++t) {
        int ia = tid + 128 * t;
        int ar = ia >> 2, ak = (ia & 3) << 2;
        oA[t] = (uint32_t)(ar * APAD + ak) * 4;
        Ag[t] = A + (size_t)(bm + ar) * lda + ak;
        int br = ia >> 5, bc = (ia & 31) << 2;
        oB[t] = (uint32_t)(br * BPAD + bc) * 4;
        Bg[t] = B + (size_t)br * ldb + bn + bc;
    }
    const uint32_t sAb = (uint32_t)__cvta_generic_to_shared(As);
    const uint32_t sBb = (uint32_t)__cvta_generic_to_shared(Bs);

    const int KT = Ku / 16;

    float acc[4][8][4];
#pragma unroll
    for (int i = 0; i < 4; ++i)
#pragma unroll
        for (int j = 0; j < 8; ++j)
#pragma unroll
            for (int r = 0; r < 4; ++r) acc[i][j][r] = 0.f;

    auto issue = [&](int kt) {
        bool v = kt < KT;
        int st = kt & (STG - 1);
        int ko = kt * 16;
        uint32_t ab = sAb + st * (ASMSZ * 4);
        uint32_t bb = sBb + st * (BSMSZ * 4);
#pragma unroll
        for (int t = 0; t < 4; ++t) cpa16z(ab + oA[t], Ag[t] + ko, v);
#pragma unroll
        for (int t = 0; t < 4; ++t) cpa16z(bb + oB[t], Bg[t] + (size_t)ko * ldb, v);
        cpa_commit();
    };

    issue(0); issue(1); issue(2);

    for (int kt = 0; kt < KT; ++kt) {
        cpa_wait<STG - 2>();
        __syncthreads();
        issue(kt + STG - 1);

        const uint32_t* Asb = As + (kt & (STG - 1)) * ASMSZ;
        const uint32_t* Bsb = Bs + (kt & (STG - 1)) * BSMSZ;
#pragma unroll
        for (int kb = 0; kb < 16; kb += 8) {
            uint32_t af[4][4], bf[8][2];
#pragma unroll
            for (int mt = 0; mt < 4; ++mt) {
                int m = wm + mt * 16 + lm;
                af[mt][0] = Asb[m * APAD + kb + lk];
                af[mt][1] = Asb[(m + 8) * APAD + kb + lk];
                af[mt][2] = Asb[m * APAD + kb + 4 + lk];
                af[mt][3] = Asb[(m + 8) * APAD + kb + 4 + lk];
            }
#pragma unroll
            for (int nt = 0; nt < 8; ++nt) {
                int n = wn + nt * 8 + lm;
                bf[nt][0] = Bsb[(kb + lk) * BPAD + n];
                bf[nt][1] = Bsb[(kb + 4 + lk) * BPAD + n];
            }
#pragma unroll
            for (int mt = 0; mt < 4; ++mt)
#pragma unroll
                for (int nt = 0; nt < 8; ++nt) {
                    asm volatile(
                        "mma.sync.aligned.m16n8k16.row.col.f32.f16.f16.f32 "
                        "{%0,%1,%2,%3}, {%4,%5,%6,%7}, {%8,%9}, {%0,%1,%2,%3};\n"
                        : "+f"(acc[mt][nt][0]), "+f"(acc[mt][nt][1]),
                          "+f"(acc[mt][nt][2]), "+f"(acc[mt][nt][3])
                        : "r"(af[mt][0]), "r"(af[mt][1]), "r"(af[mt][2]), "r"(af[mt][3]),
                          "r"(bf[nt][0]), "r"(bf[nt][1]));
                }
        }
    }

#pragma unroll
    for (int mt = 0; mt < 4; ++mt) {
#pragma unroll
        for (int nt = 0; nt < 8; ++nt) {
            int row = bm + wm + mt * 16 + lm;
            int col = bn + wn + nt * 8 + lk * 2;
            float v0 = acc[mt][nt][0], v1 = acc[mt][nt][1];
            float v2 = acc[mt][nt][2], v3 = acc[mt][nt][3];
            if (EPI == 1) {
                float bb0 = bias[col], bb1 = bias[col + 1];
                v0 += bb0; v1 += bb1; v2 += bb0; v3 += bb1;
                v0 = (v0 > 20.f) ? v0 : log1pf(expf(v0));
                v1 = (v1 > 20.f) ? v1 : log1pf(expf(v1));
                v2 = (v2 > 20.f) ? v2 : log1pf(expf(v2));
                v3 = (v3 > 20.f) ? v3 : log1pf(expf(v3));
            }
            *(float2*)(C + (size_t)row * ldc + col)       = make_float2(v0, v1);
            *(float2*)(C + (size_t)(row + 8) * ldc + col) = make_float2(v2, v3);
        }
    }
}

// ============================================================================
// split-K reduces
// ============================================================================
__global__ void reduce_dbc()
{
    int i = blockIdx.x * blockDim.x + threadIdx.x;
    if (i >= TOK * DBCW / 4) return;
    const float4* p = (const float4*)g_part;
    float4 s = p[i];
#pragma unroll
    for (int k = 1; k < KSPL; ++k) {
        float4 t = p[(size_t)k * (TOK * DBCW / 4) + i];
        s.x += t.x; s.y += t.y; s.z += t.z; s.w += t.w;
    }
    ((float4*)g_dbc)[i] = s;
    ((uint2*)g_dbch)[i] = make_uint2(pack2h(s.x, s.y), pack2h(s.z, s.w));
}

__global__ void reduce_out(float* __restrict__ out)
{
    int i = blockIdx.x * blockDim.x + threadIdx.x;
    if (i >= TOK * DM / 4) return;
    const float4* p = (const float4*)g_opart;
    float4 a = p[i];
    float4 b = p[(size_t)(TOK * DM / 4) + i];
    ((float4*)out)[i] = make_float4(a.x + b.x, a.y + b.y, a.z + b.z, a.w + b.w);
}

// ============================================================================
// Depthwise causal conv1d (k=4) + bias + SiLU -> xc (fp32 + fp16)
// ============================================================================
__global__ void conv_silu_kernel(const float* __restrict__ cw,
                                 const float* __restrict__ cb)
{
    int idx = blockIdx.x * blockDim.x + threadIdx.x;
    if (idx >= TOK * ED) return;
    int e = idx & (ED - 1);
    int t = idx >> 11;
    int l = t & (LL - 1);

    float w0 = cw[e * 4 + 0], w1 = cw[e * 4 + 1];
    float w2 = cw[e * 4 + 2], w3 = cw[e * 4 + 3];

    const float* col = g_xz + (size_t)t * (2 * ED) + e;
    float acc = cb[e] + w3 * col[0];
    if (l >= 1) acc = fmaf(w2, col[-(2 * ED)],     acc);
    if (l >= 2) acc = fmaf(w1, col[-2 * (2 * ED)], acc);
    if (l >= 3) acc = fmaf(w0, col[-3 * (2 * ED)], acc);

    float v = acc / (1.f + __expf(-acc));
    g_xc[idx]  = v;
    g_xch[idx] = __float2half_rn(v);
}

// ============================================================================
// Segmented selective scan with EXPLICIT register double-buffering
// (no runtime-indexed arrays -> no local-memory spill risk).
// ============================================================================

// ---- P1: per-segment transfer function (P, q) ----
#define LOADP1(S, L0) do {                                          \
    _Pragma("unroll")                                               \
    for (int j = 0; j < 4; ++j) {                                   \
        dv##S[j] = dptr [(size_t)((L0) + j) * ED];                  \
        xv##S[j] = xptr [(size_t)((L0) + j) * ED];                  \
        bv##S[j] = bcptr[(size_t)((L0) + j) * DBCW];                \
    }                                                               \
} while (0)

#define PROCP1(S) do {                                              \
    _Pragma("unroll")                                               \
    for (int j = 0; j < 4; ++j) {                                   \
        sumd += dv##S[j];                                           \
        float da = __expf(dv##S[j] * An);                           \
        h = fmaf(da, h, dv##S[j] * bv##S[j] * xv##S[j]);            \
    }                                                               \
} while (0)

__global__ void __launch_bounds__(256)
scan_p1(const float* __restrict__ A_log)
{
    const int tid  = threadIdx.x;
    const int g    = blockIdx.x * 16 + (tid >> 4);   // 0..32767
    const int lane = tid & 15;
    const int ed   = g & (ED - 1);
    const int sb   = g >> 11;            // b*SEG+seg
    const int b    = sb >> 3;
    const int seg  = sb & (SEG - 1);

    const float An = -__expf(A_log[ed * NS + lane]);

    const size_t tok0 = (size_t)(b * LL + seg * SEGL);
    const float* dptr  = g_delta + tok0 * ED + ed;
    const float* xptr  = g_xc    + tok0 * ED + ed;
    const float* bcptr = g_dbc   + tok0 * DBCW + DTR + lane;

    float dvA[4], xvA[4], bvA[4];
    float dvB[4], xvB[4], bvB[4];

    float h = 0.f, sumd = 0.f;
    LOADP1(A, 0);
#pragma unroll 1
    for (int l0 = 0; l0 < SEGL; l0 += 8) {
        LOADP1(B, l0 + 4);
        PROCP1(A);
        if (l0 + 8 < SEGL) LOADP1(A, l0 + 8);
        PROCP1(B);
    }
    g_segq[(size_t)g * NS + lane] = h;
    g_segP[(size_t)g * NS + lane] = __expf(An * sumd);
}

// ---- P2: combine segments -> h_start ----
__global__ void __launch_bounds__(256)
scan_p2()
{
    const int tid  = threadIdx.x;
    const int cg   = blockIdx.x * 16 + (tid >> 4);   // 0..4095
    const int lane = tid & 15;
    const int ed   = cg & (ED - 1);
    const int b    = cg >> 11;

    float hs = 0.f;
#pragma unroll
    for (int s = 0; s < SEG; ++s) {
        size_t idx = ((size_t)((b * SEG + s) * ED + ed)) * NS + lane;
        g_hst[idx] = hs;
        hs = fmaf(g_segP[idx], hs, g_segq[idx]);
    }
}

// ---- P3: full recompute with outputs ----
#define LOADP3(S, L0) do {                                          \
    _Pragma("unroll")                                               \
    for (int j = 0; j < 4; ++j) {                                   \
        dv##S[j] = dptr [(size_t)((L0) + j) * ED];                  \
        xv##S[j] = xptr [(size_t)((L0) + j) * ED];                  \
        bv##S[j] = bcptr[(size_t)((L0) + j) * DBCW];                \
        cv##S[j] = bcptr[(size_t)((L0) + j) * DBCW + NS];           \
    }                                                               \
    zv##S = zptr[(size_t)((L0) + (lane & 3)) * 2 * ED];             \
} while (0)

#define PROCP3(S, L0) do {                                          \
    float p0, p1, p2, p3, da;                                       \
    da = __expf(dv##S[0] * An); h = fmaf(da, h, dv##S[0] * bv##S[0] * xv##S[0]); p0 = h * cv##S[0]; \
    da = __expf(dv##S[1] * An); h = fmaf(da, h, dv##S[1] * bv##S[1] * xv##S[1]); p1 = h * cv##S[1]; \
    da = __expf(dv##S[2] * An); h = fmaf(da, h, dv##S[2] * bv##S[2] * xv##S[2]); p2 = h * cv##S[2]; \
    da = __expf(dv##S[3] * An); h = fmaf(da, h, dv##S[3] * bv##S[3] * xv##S[3]); p3 = h * cv##S[3]; \
    _Pragma("unroll")                                               \
    for (int m = 1; m < 16; m <<= 1) {                              \
        p0 += __shfl_xor_sync(0xffffffffu, p0, m);                  \
        p1 += __shfl_xor_sync(0xffffffffu, p1, m);                  \
        p2 += __shfl_xor_sync(0xffffffffu, p2, m);                  \
        p3 += __shfl_xor_sync(0xffffffffu, p3, m);                  \
    }                                                               \
    if (lane < 4) {                                                 \
        float p  = (lane == 0) ? p0 : (lane == 1) ? p1 : (lane == 2) ? p2 : p3; \
        float xj = (lane == 0) ? xv##S[0] : (lane == 1) ? xv##S[1]  \
                 : (lane == 2) ? xv##S[2] : xv##S[3];               \
        float sg = zv##S / (1.f + __expf(-zv##S));                  \
        yptr[(size_t)((L0) + lane) * ED] = __float2half_rn((p + Dv * xj) * sg); \
    }                                                               \
} while (0)

__global__ void __launch_bounds__(256)
scan_p3(const float* __restrict__ A_log, const float* __restrict__ Dvec)
{
    const int tid  = threadIdx.x;
    const int g    = blockIdx.x * 16 + (tid >> 4);   // 0..32767
    const int lane = tid & 15;
    const int ed   = g & (ED - 1);
    const int sb   = g >> 11;
    const int b    = sb >> 3;
    const int seg  = sb & (SEG - 1);

    const float An = -__expf(A_log[ed * NS + lane]);
    const float Dv = Dvec[ed];

    const size_t tok0 = (size_t)(b * LL + seg * SEGL);
    const float* dptr  = g_delta + tok0 * ED + ed;
    const float* xptr  = g_xc    + tok0 * ED + ed;
    const float* zptr  = g_xz    + tok0 * (2 * ED) + ED + ed;
    const float* bcptr = g_dbc   + tok0 * DBCW + DTR + lane;
    __half*      yptr  = g_yh    + tok0 * ED + ed;

    float dvA[4], xvA[4], bvA[4], cvA[4], zvA;
    float dvB[4], xvB[4], bvB[4], cvB[4], zvB;

    float h = g_hst[(size_t)g * NS + lane];
    LOADP3(A, 0);
#pragma unroll 1
    for (int l0 = 0; l0 < SEGL; l0 += 8) {
        LOADP3(B, l0 + 4);
        PROCP3(A, l0);
        if (l0 + 8 < SEGL) LOADP3(A, l0 + 8);
        PROCP3(B, l0 + 4);
    }
}

// ============================================================================
extern "C" void kernel_launch(void* const* d_in, const int* in_sizes, int n_in,
                              void* d_out, int out_size)
{
    const float* x         = (const float*)d_in[0];
    const float* in_proj_w = (const float*)d_in[1];
    const float* conv_w    = (const float*)d_in[2];
    const float* conv_b    = (const float*)d_in[3];
    const float* x_proj_w  = (const float*)d_in[4];
    const float* dt_proj_w = (const float*)d_in[5];
    const float* dt_proj_b = (const float*)d_in[6];
    const float* A_log     = (const float*)d_in[7];
    const float* Dvec      = (const float*)d_in[8];
    const float* out_proj_w= (const float*)d_in[9];
    float* out = (float*)d_out;

    static float    *p_xz = nullptr, *p_delta = nullptr, *p_part = nullptr, *p_opart = nullptr;
    static uint32_t *p_xh, *p_win, *p_wxp, *p_wdt, *p_wout, *p_xch, *p_dbch, *p_yh;
    if (!p_xz) {
        cudaGetSymbolAddress((void**)&p_xz,    g_xz);
        cudaGetSymbolAddress((void**)&p_delta, g_delta);
        cudaGetSymbolAddress((void**)&p_part,  g_part);
        cudaGetSymbolAddress((void**)&p_opart, g_opart);
        cudaGetSymbolAddress((void**)&p_xh,    g_xh);
        cudaGetSymbolAddress((void**)&p_win,   g_wh_in);
        cudaGetSymbolAddress((void**)&p_wxp,   g_wh_xp);
        cudaGetSymbolAddress((void**)&p_wdt,   g_wh_dt);
        cudaGetSymbolAddress((void**)&p_wout,  g_wh_out);
        cudaGetSymbolAddress((void**)&p_xch,   g_xch);
        cudaGetSymbolAddress((void**)&p_dbch,  g_dbch);
        cudaGetSymbolAddress((void**)&p_yh,    g_yh);
        cudaFuncSetAttribute(gemm_f16<0>, cudaFuncAttributeMaxDynamicSharedMemorySize, GEMM_SMEM);
        cudaFuncSetAttribute(gemm_f16<1>, cudaFuncAttributeMaxDynamicSharedMemorySize, GEMM_SMEM);
        cudaFuncSetAttribute(gemm_f16<3>, cudaFuncAttributeMaxDynamicSharedMemorySize, GEMM_SMEM);
    }

    // [0-1] fp16 conversions
    prep_weights<<<2048, 256>>>(in_proj_w, dt_proj_w, out_proj_w, x_proj_w);
    prep_x<<<1024, 256>>>(x);

    // [2] xz = x @ in_proj_w
    gemm_f16<0><<<dim3(2 * ED / 128, TOK / 128), 128, GEMM_SMEM>>>(
        p_xh, p_win, p_xz, TOK, 2 * ED, DM / 2, DM / 2, 2 * ED, 2 * ED, nullptr);

    // [3] depthwise causal conv + silu      <- profiled launch
    conv_silu_kernel<<<(TOK * ED + 255) / 256, 256>>>(conv_w, conv_b);

    // [4] xproj split-K
    gemm_f16<3><<<dim3(1, TOK / 128, KSPL), 128, GEMM_SMEM>>>(
        p_xch, p_wxp, p_part, TOK, DBCW, KCH / 2, ED / 2, DBCW, DBCW, nullptr);

    // [5] reduce partials -> dbc fp32 + fp16
    reduce_dbc<<<(TOK * DBCW / 4 + 255) / 256, 256>>>();

    // [6] delta = softplus(dbc[:, :64] @ dt_proj_w + b)
    gemm_f16<1><<<dim3(ED / 128, TOK / 128), 128, GEMM_SMEM>>>(
        p_dbch, p_wdt, p_delta, TOK, ED, DTR / 2, DBCW / 2, ED, ED, dt_proj_b);

    // [7-9] segmented selective scan -> y (fp16)
    scan_p1<<<BB * SEG * ED / 16, 256>>>(A_log);
    scan_p2<<<BB * ED / 16, 256>>>();
    scan_p3<<<BB * SEG * ED / 16, 256>>>(A_log, Dvec);

    // [10] out_proj split-K x2
    gemm_f16<3><<<dim3(DM / 128, TOK / 128, OSPL), 128, GEMM_SMEM>>>(
        p_yh, p_wout, p_opart, TOK, DM, ED / (2 * OSPL), ED / 2, DM, DM, nullptr);

    // [11] reduce out partials -> d_out
    reduce_out<<<(TOK * DM / 4 + 255) / 256, 256>>>(out);
}